// round 1
// baseline (speedup 1.0000x reference)
#include <cuda_runtime.h>

#define B_ 8
#define N_ 4096
#define C_ 1024
#define H_ 16
#define D_ 64
#define SCALE_ 0.125f

// Scratch (allocation-free rule: __device__ globals)
__device__ float g_qkv[(size_t)3 * B_ * N_ * C_];   // Q,K,V in natural (B,N,C) layout
__device__ float g_o[(size_t)B_ * N_ * C_];         // attention out, pre-permuted for final GEMM

// ---------- packed f32x2 helpers (Blackwell FFMA2) ----------
__device__ __forceinline__ unsigned long long pk2(float x, float y) {
    unsigned long long r;
    asm("mov.b64 %0, {%1, %2};" : "=l"(r)
        : "r"(__float_as_uint(x)), "r"(__float_as_uint(y)));
    return r;
}
__device__ __forceinline__ void fma2(unsigned long long& c, unsigned long long a,
                                     unsigned long long b) {
    asm("fma.rn.f32x2 %0, %1, %2, %0;" : "+l"(c) : "l"(a), "l"(b));
}
__device__ __forceinline__ float2 upk2(unsigned long long v) {
    unsigned int lo, hi;
    asm("mov.b64 {%0, %1}, %2;" : "=r"(lo), "=r"(hi) : "l"(v));
    return make_float2(__uint_as_float(lo), __uint_as_float(hi));
}

// ---------- C = A * W^T (+bias), A: MxK row-major, W: NxK row-major ----------
// 128x128 block, BK=16, 256 threads, 8x8 per-thread microtile, FFMA2 inner loop.
template <bool BIAS>
__global__ __launch_bounds__(256, 2) void sgemm_nt(
    const float* __restrict__ A, const float* __restrict__ W,
    const float* __restrict__ bias, float* __restrict__ C,
    int M, int Nn, int K)
{
    __shared__ float As[16][132];
    __shared__ float Bs[16][132];
    const int tid = threadIdx.x;
    const int tx = tid & 15, ty = tid >> 4;
    const size_t bm = (size_t)blockIdx.y * 128;
    const size_t bn = (size_t)blockIdx.x * 128;
    const float* Ap = A + bm * K;
    const float* Wp = W + bn * K;

    unsigned long long acc[8][4];
#pragma unroll
    for (int i = 0; i < 8; i++)
#pragma unroll
        for (int j = 0; j < 4; j++) acc[i][j] = 0ull;

    for (int kt = 0; kt < K; kt += 16) {
#pragma unroll
        for (int t = 0; t < 2; t++) {
            int fid = tid + t * 256;          // 0..511
            int row = fid >> 2;               // 0..127
            int kq  = (fid & 3) << 2;         // 0,4,8,12
            float4 va = *reinterpret_cast<const float4*>(Ap + (size_t)row * K + kt + kq);
            As[kq + 0][row] = va.x; As[kq + 1][row] = va.y;
            As[kq + 2][row] = va.z; As[kq + 3][row] = va.w;
            float4 vb = *reinterpret_cast<const float4*>(Wp + (size_t)row * K + kt + kq);
            Bs[kq + 0][row] = vb.x; Bs[kq + 1][row] = vb.y;
            Bs[kq + 2][row] = vb.z; Bs[kq + 3][row] = vb.w;
        }
        __syncthreads();
#pragma unroll
        for (int k = 0; k < 16; k++) {
            float4 a0 = *reinterpret_cast<const float4*>(&As[k][ty * 4]);
            float4 a1 = *reinterpret_cast<const float4*>(&As[k][64 + ty * 4]);
            float4 b0 = *reinterpret_cast<const float4*>(&Bs[k][tx * 4]);
            float4 b1 = *reinterpret_cast<const float4*>(&Bs[k][64 + tx * 4]);
            unsigned long long bp0 = pk2(b0.x, b0.y), bp1 = pk2(b0.z, b0.w);
            unsigned long long bp2 = pk2(b1.x, b1.y), bp3 = pk2(b1.z, b1.w);
            float av[8] = {a0.x, a0.y, a0.z, a0.w, a1.x, a1.y, a1.z, a1.w};
#pragma unroll
            for (int i = 0; i < 8; i++) {
                unsigned long long ad = pk2(av[i], av[i]);
                fma2(acc[i][0], ad, bp0);
                fma2(acc[i][1], ad, bp1);
                fma2(acc[i][2], ad, bp2);
                fma2(acc[i][3], ad, bp3);
            }
        }
        __syncthreads();
    }

    float4 bb0 = make_float4(0.f, 0.f, 0.f, 0.f), bb1 = bb0;
    if (BIAS) {
        bb0 = *reinterpret_cast<const float4*>(bias + bn + tx * 4);
        bb1 = *reinterpret_cast<const float4*>(bias + bn + 64 + tx * 4);
    }
#pragma unroll
    for (int i = 0; i < 8; i++) {
        size_t row = bm + (i < 4 ? (size_t)(ty * 4 + i) : (size_t)(64 + ty * 4 + (i - 4)));
        float2 c0 = upk2(acc[i][0]), c1 = upk2(acc[i][1]);
        float2 c2 = upk2(acc[i][2]), c3 = upk2(acc[i][3]);
        float4 o0 = make_float4(c0.x + bb0.x, c0.y + bb0.y, c1.x + bb0.z, c1.y + bb0.w);
        float4 o1 = make_float4(c2.x + bb1.x, c2.y + bb1.y, c3.x + bb1.z, c3.y + bb1.w);
        *reinterpret_cast<float4*>(C + row * Nn + bn + tx * 4) = o0;
        *reinterpret_cast<float4*>(C + row * Nn + bn + 64 + tx * 4) = o1;
    }
}

// ---------- fused head-dim attention: one block per (b,h) ----------
// S[d][e] = sum_n Q[b,n,h*64+d] * K[b,n,h*64+e]; P = softmax(S*SCALE, rows d over e);
// O[d][n] = sum_e P[d][e] * V[b,n,h*64+e], written at b<<22 | d<<16 | h<<12 | n
// (this IS the transpose(0,2,1,3).reshape layout, so the final GEMM is plain row-major).
__global__ __launch_bounds__(256) void attn_kernel(const float* __restrict__ qkv,
                                                   float* __restrict__ O)
{
    __shared__ float Qs[64][64];   // phase1: Q tile; afterwards: P (64x64)
    __shared__ float Ks[64][68];   // phase1: K tile; phase2: V^T tile (Vs[e][nl])
    const int tid = threadIdx.x;
    const int tx = tid & 15, ty = tid >> 4;
    const int b = blockIdx.x >> 4, h = blockIdx.x & 15;
    const float* Q  = qkv + (size_t)b * (N_ * C_) + h * 64;
    const float* Kp = qkv + (size_t)(B_ + b) * (N_ * C_) + h * 64;
    const float* V  = qkv + (size_t)(2 * B_ + b) * (N_ * C_) + h * 64;

    unsigned long long s2[4][2];
#pragma unroll
    for (int i = 0; i < 4; i++) { s2[i][0] = 0ull; s2[i][1] = 0ull; }

    // ---- phase 1: S = Q K^T (reduce over all 4096 tokens, 64 at a time) ----
    for (int n0 = 0; n0 < N_; n0 += 64) {
#pragma unroll
        for (int t = 0; t < 4; t++) {
            int fid = tid + t * 256;          // 0..1023
            int nl  = fid >> 4;               // 0..63
            int c4  = (fid & 15) << 2;        // 0..60
            *reinterpret_cast<float4*>(&Qs[nl][c4]) =
                *reinterpret_cast<const float4*>(Q + (size_t)(n0 + nl) * C_ + c4);
            *reinterpret_cast<float4*>(&Ks[nl][c4]) =
                *reinterpret_cast<const float4*>(Kp + (size_t)(n0 + nl) * C_ + c4);
        }
        __syncthreads();
#pragma unroll 8
        for (int nl = 0; nl < 64; nl++) {
            float4 a  = *reinterpret_cast<const float4*>(&Qs[nl][tx * 4]);   // d
            float4 bk = *reinterpret_cast<const float4*>(&Ks[nl][ty * 4]);   // e
            unsigned long long e0 = pk2(bk.x, bk.y), e1 = pk2(bk.z, bk.w);
            float av[4] = {a.x, a.y, a.z, a.w};
#pragma unroll
            for (int i = 0; i < 4; i++) {
                unsigned long long ad = pk2(av[i], av[i]);
                fma2(s2[i][0], ad, e0);
                fma2(s2[i][1], ad, e1);
            }
        }
        __syncthreads();
    }

    // write scaled logits into Qs (as S[d][e]); thread owns d = tx*4+i, e = ty*4..+3
#pragma unroll
    for (int i = 0; i < 4; i++) {
        float2 u0 = upk2(s2[i][0]), u1 = upk2(s2[i][1]);
        *reinterpret_cast<float4*>(&Qs[tx * 4 + i][ty * 4]) =
            make_float4(u0.x * SCALE_, u0.y * SCALE_, u1.x * SCALE_, u1.y * SCALE_);
    }
    __syncthreads();

    // ---- softmax over e (row-wise), 8 warps x 8 rows ----
    {
        int warp = tid >> 5, lane = tid & 31;
        for (int r = warp; r < 64; r += 8) {
            float v0 = Qs[r][lane], v1 = Qs[r][lane + 32];
            float m = fmaxf(v0, v1);
#pragma unroll
            for (int off = 16; off; off >>= 1) m = fmaxf(m, __shfl_xor_sync(0xffffffffu, m, off));
            float e0 = expf(v0 - m), e1 = expf(v1 - m);
            float ssum = e0 + e1;
#pragma unroll
            for (int off = 16; off; off >>= 1) ssum += __shfl_xor_sync(0xffffffffu, ssum, off);
            float inv = 1.0f / ssum;
            Qs[r][lane] = e0 * inv;
            Qs[r][lane + 32] = e1 * inv;
        }
    }
    __syncthreads();

    // ---- phase 2: O = P V, streamed over token chunks of 64 ----
    float* ob = O + ((size_t)b << 22) + ((size_t)h << 12);
    for (int n0 = 0; n0 < N_; n0 += 64) {
#pragma unroll
        for (int t = 0; t < 4; t++) {
            int fid = tid + t * 256;
            int nl  = fid >> 4;
            int e4  = (fid & 15) << 2;
            float4 v = *reinterpret_cast<const float4*>(V + (size_t)(n0 + nl) * C_ + e4);
            Ks[e4 + 0][nl] = v.x; Ks[e4 + 1][nl] = v.y;   // V^T: Vs[e][nl]
            Ks[e4 + 2][nl] = v.z; Ks[e4 + 3][nl] = v.w;
        }
        __syncthreads();
        unsigned long long o2[4][2];
#pragma unroll
        for (int i = 0; i < 4; i++) { o2[i][0] = 0ull; o2[i][1] = 0ull; }
#pragma unroll 4
        for (int e = 0; e < 64; e += 4) {
            float4 p0 = *reinterpret_cast<const float4*>(&Qs[ty * 4 + 0][e]);
            float4 p1 = *reinterpret_cast<const float4*>(&Qs[ty * 4 + 1][e]);
            float4 p2 = *reinterpret_cast<const float4*>(&Qs[ty * 4 + 2][e]);
            float4 p3 = *reinterpret_cast<const float4*>(&Qs[ty * 4 + 3][e]);
            float4 v0 = *reinterpret_cast<const float4*>(&Ks[e + 0][tx * 4]);
            float4 v1 = *reinterpret_cast<const float4*>(&Ks[e + 1][tx * 4]);
            float4 v2 = *reinterpret_cast<const float4*>(&Ks[e + 2][tx * 4]);
            float4 v3 = *reinterpret_cast<const float4*>(&Ks[e + 3][tx * 4]);
            unsigned long long vq[4][2] = {
                {pk2(v0.x, v0.y), pk2(v0.z, v0.w)},
                {pk2(v1.x, v1.y), pk2(v1.z, v1.w)},
                {pk2(v2.x, v2.y), pk2(v2.z, v2.w)},
                {pk2(v3.x, v3.y), pk2(v3.z, v3.w)}};
            float pr[4][4] = {{p0.x, p0.y, p0.z, p0.w},
                              {p1.x, p1.y, p1.z, p1.w},
                              {p2.x, p2.y, p2.z, p2.w},
                              {p3.x, p3.y, p3.z, p3.w}};
#pragma unroll
            for (int i = 0; i < 4; i++) {
#pragma unroll
                for (int q = 0; q < 4; q++) {
                    unsigned long long pd = pk2(pr[i][q], pr[i][q]);
                    fma2(o2[i][0], pd, vq[q][0]);
                    fma2(o2[i][1], pd, vq[q][1]);
                }
            }
        }
        __syncthreads();
#pragma unroll
        for (int i = 0; i < 4; i++) {
            int d = ty * 4 + i;
            float2 u0 = upk2(o2[i][0]), u1 = upk2(o2[i][1]);
            *reinterpret_cast<float4*>(ob + ((size_t)d << 16) + n0 + tx * 4) =
                make_float4(u0.x, u0.y, u1.x, u1.y);
        }
    }
}

extern "C" void kernel_launch(void* const* d_in, const int* in_sizes, int n_in,
                              void* d_out, int out_size)
{
    const float* x  = (const float*)d_in[0];
    const float* Wq = (const float*)d_in[1];
    const float* Wk = (const float*)d_in[2];
    const float* Wv = (const float*)d_in[3];
    const float* Wp = (const float*)d_in[4];
    const float* bp = (const float*)d_in[5];
    float* out = (float*)d_out;

    float *qkv = nullptr, *ob = nullptr;
    cudaGetSymbolAddress((void**)&qkv, g_qkv);
    cudaGetSymbolAddress((void**)&ob, g_o);

    const int M = B_ * N_;
    dim3 grid(C_ / 128, M / 128);

    sgemm_nt<false><<<grid, 256>>>(x, Wq, nullptr, qkv, M, C_, C_);
    sgemm_nt<false><<<grid, 256>>>(x, Wk, nullptr, qkv + (size_t)M * C_, M, C_, C_);
    sgemm_nt<false><<<grid, 256>>>(x, Wv, nullptr, qkv + (size_t)2 * M * C_, M, C_, C_);
    attn_kernel<<<B_ * H_, 256>>>(qkv, ob);
    sgemm_nt<true><<<grid, 256>>>(ob, Wp, bp, out, M, C_, C_);
}

// round 5
// speedup vs baseline: 2.0158x; 2.0158x over previous
#include <cuda_runtime.h>
#include <cuda_bf16.h>
#include <cstdint>

#define B_ 8
#define N_ 4096
#define C_ 1024
#define H_ 16
#define SCALE_ 0.125f
#define M_ (B_ * N_)          // 32768 rows
#define K2_ 2048              // stored split K (hi|lo)
#define NCHUNK 48             // virtual K = 3072 (hi*hi + lo*hi + hi*lo)

// ---------------- scratch (__device__ globals; no allocs allowed) ----------------
__device__ __align__(16) __nv_bfloat16 g_x2[(size_t)M_ * K2_];        // x split
__device__ __align__(16) __nv_bfloat16 g_w2[4][(size_t)C_ * K2_];     // Wq,Wk,Wv,Wp split
__device__ float g_qkv[(size_t)3 * M_ * C_];                          // Q,K,V fp32 (B,N,C)
__device__ float g_o[(size_t)M_ * C_];                                // attn out (pre-permuted)
__device__ __align__(16) __nv_bfloat16 g_o2[(size_t)M_ * K2_];        // attn out split

// ---------------- helpers ----------------
__device__ __forceinline__ uint32_t smem_u32(const void* p) {
    uint32_t a;
    asm("{ .reg .u64 t; cvta.to.shared.u64 t, %1; cvt.u32.u64 %0, t; }" : "=r"(a) : "l"(p));
    return a;
}
__device__ __forceinline__ uint32_t swz(uint32_t off) {   // 128B-row XOR swizzle
    return off ^ ((off >> 3) & 0x70);
}
__device__ __forceinline__ void ldsm4(uint32_t* r, uint32_t addr) {
    asm volatile("ldmatrix.sync.aligned.m8n8.x4.shared.b16 {%0,%1,%2,%3}, [%4];"
                 : "=r"(r[0]), "=r"(r[1]), "=r"(r[2]), "=r"(r[3]) : "r"(addr));
}
__device__ __forceinline__ void mma16816(float* d, const uint32_t* a, uint32_t b0, uint32_t b1) {
    asm volatile("mma.sync.aligned.m16n8k16.row.col.f32.bf16.bf16.f32 "
                 "{%0,%1,%2,%3}, {%4,%5,%6,%7}, {%8,%9}, {%0,%1,%2,%3};"
                 : "+f"(d[0]), "+f"(d[1]), "+f"(d[2]), "+f"(d[3])
                 : "r"(a[0]), "r"(a[1]), "r"(a[2]), "r"(a[3]), "r"(b0), "r"(b1));
}
__device__ __forceinline__ void cpasync16(uint32_t dst, const void* src) {
    asm volatile("cp.async.cg.shared.global [%0], [%1], 16;" :: "r"(dst), "l"(src));
}

// ---------- packed f32x2 helpers (attention kernel) ----------
__device__ __forceinline__ unsigned long long pk2(float x, float y) {
    unsigned long long r;
    asm("mov.b64 %0, {%1, %2};" : "=l"(r)
        : "r"(__float_as_uint(x)), "r"(__float_as_uint(y)));
    return r;
}
__device__ __forceinline__ void fma2(unsigned long long& c, unsigned long long a,
                                     unsigned long long b) {
    asm("fma.rn.f32x2 %0, %1, %2, %0;" : "+l"(c) : "l"(a), "l"(b));
}
__device__ __forceinline__ float2 upk2(unsigned long long v) {
    unsigned int lo, hi;
    asm("mov.b64 {%0, %1}, %2;" : "=r"(lo), "=r"(hi) : "l"(v));
    return make_float2(__uint_as_float(lo), __uint_as_float(hi));
}

// ---------------- split fp32 -> [hi | lo] bf16, row width 1024 -> 2048 ----------------
__global__ void split_kernel(const float4* __restrict__ in, __nv_bfloat16* __restrict__ out,
                             int n4) {
    int i = blockIdx.x * blockDim.x + threadIdx.x;
    if (i >= n4) return;
    int r = i >> 8;              // 256 float4 per 1024-col row
    int c = (i & 255) << 2;
    float4 v = in[i];
    __nv_bfloat16 h0 = __float2bfloat16(v.x), h1 = __float2bfloat16(v.y);
    __nv_bfloat16 h2 = __float2bfloat16(v.z), h3 = __float2bfloat16(v.w);
    __nv_bfloat16 l0 = __float2bfloat16(v.x - __bfloat162float(h0));
    __nv_bfloat16 l1 = __float2bfloat16(v.y - __bfloat162float(h1));
    __nv_bfloat16 l2 = __float2bfloat16(v.z - __bfloat162float(h2));
    __nv_bfloat16 l3 = __float2bfloat16(v.w - __bfloat162float(h3));
    __nv_bfloat162* oh = reinterpret_cast<__nv_bfloat162*>(out + (size_t)r * K2_ + c);
    __nv_bfloat162* ol = reinterpret_cast<__nv_bfloat162*>(out + (size_t)r * K2_ + 1024 + c);
    oh[0] = __nv_bfloat162(h0, h1); oh[1] = __nv_bfloat162(h2, h3);
    ol[0] = __nv_bfloat162(l0, l1); ol[1] = __nv_bfloat162(l2, l3);
}

// ---------------- HMMA bf16 GEMM: C = A*W^T (+bias), 3-term split precision ----------------
// Virtual K = 3072 via source-column remap:
//   chunks  0-15: Ahi * Bhi     chunks 16-31: Alo * Bhi     chunks 32-47: Ahi * Blo
// CTA 128x128, BK=64 (128B rows, swizzled), 3-stage cp.async, warp 32x64 (4x2 warps).
#define STAGE_BYTES 32768
#define GSMEM_SZ (3 * STAGE_BYTES)

template <bool BIAS>
__global__ __launch_bounds__(256, 2) void gemm_mma(
    const __nv_bfloat16* __restrict__ A, const __nv_bfloat16* __restrict__ Bw,
    const float* __restrict__ bias, float* __restrict__ C)
{
    extern __shared__ char smem[];
    const uint32_t sb = smem_u32(smem);
    const int tid = threadIdx.x, lane = tid & 31, wid = tid >> 5;
    const int wm = wid & 3, wn = wid >> 2;                 // 4 x 2 warp grid
    const size_t bm = (size_t)blockIdx.y * 128;
    const size_t bn = (size_t)blockIdx.x * 128;

    // cp.async plan: thread loads 4x16B for A, 4x16B for B per stage
    const int lrow = tid >> 3;                              // 0..31
    const __nv_bfloat16* Ag = A + (bm + lrow) * K2_ + (tid & 7) * 8;
    const __nv_bfloat16* Bg = Bw + (bn + lrow) * K2_ + (tid & 7) * 8;
    const uint32_t aOff = swz((uint32_t)(lrow * 128 + (tid & 7) * 16));

    // ldmatrix plan
    const int qrow = lane & 15;
    const uint32_t khalf = (uint32_t)((lane >> 4) << 4);    // 0 or 16 bytes
    const uint32_t axor = (uint32_t)((qrow & 7) << 4);

    float acc[2][8][4];
#pragma unroll
    for (int mf = 0; mf < 2; mf++)
#pragma unroll
        for (int nf = 0; nf < 8; nf++)
#pragma unroll
            for (int j = 0; j < 4; j++) acc[mf][nf][j] = 0.f;

    // source-column remap for the 3-term split
    auto kA = [](int i) { return (i < 32 ? i : i - 32) * 64; };
    auto kB = [](int i) { return (i < 16 ? i : i - 16) * 64; };

    auto issue = [&](int s, int i) {
        uint32_t ad = sb + s * STAGE_BYTES + aOff;
        uint32_t bd = ad + 16384;
        const __nv_bfloat16* ag = Ag + kA(i);
        const __nv_bfloat16* bg = Bg + kB(i);
#pragma unroll
        for (int t = 0; t < 4; t++) {
            cpasync16(ad + t * 4096, ag + (size_t)t * 32 * K2_);
            cpasync16(bd + t * 4096, bg + (size_t)t * 32 * K2_);
        }
        asm volatile("cp.async.commit_group;");
    };

    issue(0, 0);
    issue(1, 1);

    for (int i = 0; i < NCHUNK; i++) {
        asm volatile("cp.async.wait_group 1;");
        __syncthreads();
        if (i + 2 < NCHUNK) issue((i + 2) % 3, i + 2);

        const uint32_t Ab = sb + (i % 3) * STAGE_BYTES;
        const uint32_t Bb = Ab + 16384;
#pragma unroll
        for (int ks = 0; ks < 4; ks++) {
            const uint32_t kb = (uint32_t)(ks * 32) + khalf;
            uint32_t af[2][4];
#pragma unroll
            for (int mf = 0; mf < 2; mf++)
                ldsm4(af[mf], Ab + (uint32_t)((wm * 32 + mf * 16 + qrow) * 128) + (kb ^ axor));
#pragma unroll
            for (int np = 0; np < 4; np++) {
                uint32_t r[4];
                ldsm4(r, Bb + (uint32_t)((wn * 64 + np * 16 + qrow) * 128) + (kb ^ axor));
#pragma unroll
                for (int mf = 0; mf < 2; mf++) {
                    mma16816(acc[mf][2 * np + 0], af[mf], r[0], r[2]);
                    mma16816(acc[mf][2 * np + 1], af[mf], r[1], r[3]);
                }
            }
        }
    }

    // epilogue
#pragma unroll
    for (int mf = 0; mf < 2; mf++) {
        const size_t row0 = bm + wm * 32 + mf * 16 + (lane >> 2);
#pragma unroll
        for (int nf = 0; nf < 8; nf++) {
            const int col = (int)bn + wn * 64 + nf * 8 + (lane & 3) * 2;
            float bx = 0.f, by = 0.f;
            if (BIAS) { bx = bias[col]; by = bias[col + 1]; }
            *reinterpret_cast<float2*>(C + row0 * C_ + col) =
                make_float2(acc[mf][nf][0] + bx, acc[mf][nf][1] + by);
            *reinterpret_cast<float2*>(C + (row0 + 8) * C_ + col) =
                make_float2(acc[mf][nf][2] + bx, acc[mf][nf][3] + by);
        }
    }
}

// ---------------- fused head-dim attention (unchanged, verified in R1) ----------------
__global__ __launch_bounds__(256) void attn_kernel(const float* __restrict__ qkv,
                                                   float* __restrict__ O)
{
    __shared__ float Qs[64][64];
    __shared__ float Ks[64][68];
    const int tid = threadIdx.x;
    const int tx = tid & 15, ty = tid >> 4;
    const int b = blockIdx.x >> 4, h = blockIdx.x & 15;
    const float* Q  = qkv + (size_t)b * (N_ * C_) + h * 64;
    const float* Kp = qkv + (size_t)(B_ + b) * (N_ * C_) + h * 64;
    const float* V  = qkv + (size_t)(2 * B_ + b) * (N_ * C_) + h * 64;

    unsigned long long s2[4][2];
#pragma unroll
    for (int i = 0; i < 4; i++) { s2[i][0] = 0ull; s2[i][1] = 0ull; }

    for (int n0 = 0; n0 < N_; n0 += 64) {
#pragma unroll
        for (int t = 0; t < 4; t++) {
            int fid = tid + t * 256;
            int nl  = fid >> 4;
            int c4  = (fid & 15) << 2;
            *reinterpret_cast<float4*>(&Qs[nl][c4]) =
                *reinterpret_cast<const float4*>(Q + (size_t)(n0 + nl) * C_ + c4);
            *reinterpret_cast<float4*>(&Ks[nl][c4]) =
                *reinterpret_cast<const float4*>(Kp + (size_t)(n0 + nl) * C_ + c4);
        }
        __syncthreads();
#pragma unroll 8
        for (int nl = 0; nl < 64; nl++) {
            float4 a  = *reinterpret_cast<const float4*>(&Qs[nl][tx * 4]);
            float4 bk = *reinterpret_cast<const float4*>(&Ks[nl][ty * 4]);
            unsigned long long e0 = pk2(bk.x, bk.y), e1 = pk2(bk.z, bk.w);
            float av[4] = {a.x, a.y, a.z, a.w};
#pragma unroll
            for (int i = 0; i < 4; i++) {
                unsigned long long ad = pk2(av[i], av[i]);
                fma2(s2[i][0], ad, e0);
                fma2(s2[i][1], ad, e1);
            }
        }
        __syncthreads();
    }

#pragma unroll
    for (int i = 0; i < 4; i++) {
        float2 u0 = upk2(s2[i][0]), u1 = upk2(s2[i][1]);
        *reinterpret_cast<float4*>(&Qs[tx * 4 + i][ty * 4]) =
            make_float4(u0.x * SCALE_, u0.y * SCALE_, u1.x * SCALE_, u1.y * SCALE_);
    }
    __syncthreads();

    {
        int warp = tid >> 5, lane = tid & 31;
        for (int r = warp; r < 64; r += 8) {
            float v0 = Qs[r][lane], v1 = Qs[r][lane + 32];
            float m = fmaxf(v0, v1);
#pragma unroll
            for (int off = 16; off; off >>= 1) m = fmaxf(m, __shfl_xor_sync(0xffffffffu, m, off));
            float e0 = expf(v0 - m), e1 = expf(v1 - m);
            float ssum = e0 + e1;
#pragma unroll
            for (int off = 16; off; off >>= 1) ssum += __shfl_xor_sync(0xffffffffu, ssum, off);
            float inv = 1.0f / ssum;
            Qs[r][lane] = e0 * inv;
            Qs[r][lane + 32] = e1 * inv;
        }
    }
    __syncthreads();

    float* ob = O + ((size_t)b << 22) + ((size_t)h << 12);
    for (int n0 = 0; n0 < N_; n0 += 64) {
#pragma unroll
        for (int t = 0; t < 4; t++) {
            int fid = tid + t * 256;
            int nl  = fid >> 4;
            int e4  = (fid & 15) << 2;
            float4 v = *reinterpret_cast<const float4*>(V + (size_t)(n0 + nl) * C_ + e4);
            Ks[e4 + 0][nl] = v.x; Ks[e4 + 1][nl] = v.y;
            Ks[e4 + 2][nl] = v.z; Ks[e4 + 3][nl] = v.w;
        }
        __syncthreads();
        unsigned long long o2[4][2];
#pragma unroll
        for (int i = 0; i < 4; i++) { o2[i][0] = 0ull; o2[i][1] = 0ull; }
#pragma unroll 4
        for (int e = 0; e < 64; e += 4) {
            float4 p0 = *reinterpret_cast<const float4*>(&Qs[ty * 4 + 0][e]);
            float4 p1 = *reinterpret_cast<const float4*>(&Qs[ty * 4 + 1][e]);
            float4 p2 = *reinterpret_cast<const float4*>(&Qs[ty * 4 + 2][e]);
            float4 p3 = *reinterpret_cast<const float4*>(&Qs[ty * 4 + 3][e]);
            float4 v0 = *reinterpret_cast<const float4*>(&Ks[e + 0][tx * 4]);
            float4 v1 = *reinterpret_cast<const float4*>(&Ks[e + 1][tx * 4]);
            float4 v2 = *reinterpret_cast<const float4*>(&Ks[e + 2][tx * 4]);
            float4 v3 = *reinterpret_cast<const float4*>(&Ks[e + 3][tx * 4]);
            unsigned long long vq[4][2] = {
                {pk2(v0.x, v0.y), pk2(v0.z, v0.w)},
                {pk2(v1.x, v1.y), pk2(v1.z, v1.w)},
                {pk2(v2.x, v2.y), pk2(v2.z, v2.w)},
                {pk2(v3.x, v3.y), pk2(v3.z, v3.w)}};
            float pr[4][4] = {{p0.x, p0.y, p0.z, p0.w},
                              {p1.x, p1.y, p1.z, p1.w},
                              {p2.x, p2.y, p2.z, p2.w},
                              {p3.x, p3.y, p3.z, p3.w}};
#pragma unroll
            for (int i = 0; i < 4; i++) {
#pragma unroll
                for (int q = 0; q < 4; q++) {
                    unsigned long long pd = pk2(pr[i][q], pr[i][q]);
                    fma2(o2[i][0], pd, vq[q][0]);
                    fma2(o2[i][1], pd, vq[q][1]);
                }
            }
        }
        __syncthreads();
#pragma unroll
        for (int i = 0; i < 4; i++) {
            int d = ty * 4 + i;
            float2 u0 = upk2(o2[i][0]), u1 = upk2(o2[i][1]);
            *reinterpret_cast<float4*>(ob + ((size_t)d << 16) + n0 + tx * 4) =
                make_float4(u0.x, u0.y, u1.x, u1.y);
        }
    }
}

extern "C" void kernel_launch(void* const* d_in, const int* in_sizes, int n_in,
                              void* d_out, int out_size)
{
    const float* x  = (const float*)d_in[0];
    const float* Wq = (const float*)d_in[1];
    const float* Wk = (const float*)d_in[2];
    const float* Wv = (const float*)d_in[3];
    const float* Wp = (const float*)d_in[4];
    const float* bp = (const float*)d_in[5];
    float* out = (float*)d_out;

    __nv_bfloat16 *x2 = nullptr, *w2 = nullptr, *o2 = nullptr;
    float *qkv = nullptr, *ob = nullptr;
    cudaGetSymbolAddress((void**)&x2, g_x2);
    cudaGetSymbolAddress((void**)&w2, g_w2);
    cudaGetSymbolAddress((void**)&qkv, g_qkv);
    cudaGetSymbolAddress((void**)&ob, g_o);
    cudaGetSymbolAddress((void**)&o2, g_o2);

    cudaFuncSetAttribute(gemm_mma<false>, cudaFuncAttributeMaxDynamicSharedMemorySize, GSMEM_SZ);
    cudaFuncSetAttribute(gemm_mma<true>,  cudaFuncAttributeMaxDynamicSharedMemorySize, GSMEM_SZ);

    const size_t wStride = (size_t)C_ * K2_;

    // split inputs
    split_kernel<<<(M_ * C_ / 4 + 255) / 256, 256>>>((const float4*)x, x2, M_ * C_ / 4);
    split_kernel<<<(C_ * C_ / 4 + 255) / 256, 256>>>((const float4*)Wq, w2 + 0 * wStride, C_ * C_ / 4);
    split_kernel<<<(C_ * C_ / 4 + 255) / 256, 256>>>((const float4*)Wk, w2 + 1 * wStride, C_ * C_ / 4);
    split_kernel<<<(C_ * C_ / 4 + 255) / 256, 256>>>((const float4*)Wv, w2 + 2 * wStride, C_ * C_ / 4);
    split_kernel<<<(C_ * C_ / 4 + 255) / 256, 256>>>((const float4*)Wp, w2 + 3 * wStride, C_ * C_ / 4);

    dim3 grid(C_ / 128, M_ / 128);
    gemm_mma<false><<<grid, 256, GSMEM_SZ>>>(x2, w2 + 0 * wStride, nullptr, qkv);
    gemm_mma<false><<<grid, 256, GSMEM_SZ>>>(x2, w2 + 1 * wStride, nullptr, qkv + (size_t)M_ * C_);
    gemm_mma<false><<<grid, 256, GSMEM_SZ>>>(x2, w2 + 2 * wStride, nullptr, qkv + (size_t)2 * M_ * C_);

    attn_kernel<<<B_ * H_, 256>>>(qkv, ob);

    split_kernel<<<(M_ * C_ / 4 + 255) / 256, 256>>>((const float4*)ob, o2, M_ * C_ / 4);
    gemm_mma<true><<<grid, 256, GSMEM_SZ>>>(o2, w2 + 3 * wStride, bp, out);
}

// round 6
// speedup vs baseline: 2.0411x; 1.0125x over previous
#include <cuda_runtime.h>
#include <cuda_bf16.h>
#include <cstdint>

#define B_ 8
#define N_ 4096
#define C_ 1024
#define H_ 16
#define SCALE_ 0.125f
#define M_ (B_ * N_)          // 32768 rows
#define K2_ 2048              // stored split K (hi|lo)
#define NCHUNK 48             // virtual K = 3072 (hi*hi + lo*hi + hi*lo)

// ---------------- scratch (__device__ globals; no allocs allowed) ----------------
__device__ __align__(16) __nv_bfloat16 g_x2[(size_t)M_ * K2_];        // x split
__device__ __align__(16) __nv_bfloat16 g_w2[4][(size_t)C_ * K2_];     // Wq,Wk,Wv,Wp split
__device__ float g_qkv[(size_t)3 * M_ * C_];                          // Q,K,V fp32 (B,N,C)
__device__ float g_sp[(size_t)128 * 4 * 4096];                        // S partials (b,h,chunk)
__device__ float g_p[(size_t)128 * 4096];                             // softmaxed P
__device__ __align__(16) __nv_bfloat16 g_o2[(size_t)M_ * K2_];        // attn out split (direct)

// ---------------- helpers ----------------
__device__ __forceinline__ uint32_t smem_u32(const void* p) {
    uint32_t a;
    asm("{ .reg .u64 t; cvta.to.shared.u64 t, %1; cvt.u32.u64 %0, t; }" : "=r"(a) : "l"(p));
    return a;
}
__device__ __forceinline__ uint32_t swz(uint32_t off) {   // 128B-row XOR swizzle
    return off ^ ((off >> 3) & 0x70);
}
__device__ __forceinline__ void ldsm4(uint32_t* r, uint32_t addr) {
    asm volatile("ldmatrix.sync.aligned.m8n8.x4.shared.b16 {%0,%1,%2,%3}, [%4];"
                 : "=r"(r[0]), "=r"(r[1]), "=r"(r[2]), "=r"(r[3]) : "r"(addr));
}
__device__ __forceinline__ void mma16816(float* d, const uint32_t* a, uint32_t b0, uint32_t b1) {
    asm volatile("mma.sync.aligned.m16n8k16.row.col.f32.bf16.bf16.f32 "
                 "{%0,%1,%2,%3}, {%4,%5,%6,%7}, {%8,%9}, {%0,%1,%2,%3};"
                 : "+f"(d[0]), "+f"(d[1]), "+f"(d[2]), "+f"(d[3])
                 : "r"(a[0]), "r"(a[1]), "r"(a[2]), "r"(a[3]), "r"(b0), "r"(b1));
}
__device__ __forceinline__ void cpasync16(uint32_t dst, const void* src) {
    asm volatile("cp.async.cg.shared.global [%0], [%1], 16;" :: "r"(dst), "l"(src));
}

// ---------- packed f32x2 helpers ----------
__device__ __forceinline__ unsigned long long pk2(float x, float y) {
    unsigned long long r;
    asm("mov.b64 %0, {%1, %2};" : "=l"(r)
        : "r"(__float_as_uint(x)), "r"(__float_as_uint(y)));
    return r;
}
__device__ __forceinline__ void fma2(unsigned long long& c, unsigned long long a,
                                     unsigned long long b) {
    asm("fma.rn.f32x2 %0, %1, %2, %0;" : "+l"(c) : "l"(a), "l"(b));
}
__device__ __forceinline__ float2 upk2(unsigned long long v) {
    unsigned int lo, hi;
    asm("mov.b64 {%0, %1}, %2;" : "=r"(lo), "=r"(hi) : "l"(v));
    return make_float2(__uint_as_float(lo), __uint_as_float(hi));
}

// ---------------- split fp32 -> [hi | lo] bf16, row width 1024 -> 2048 ----------------
__global__ void split_kernel(const float4* __restrict__ in, __nv_bfloat16* __restrict__ out,
                             int n4) {
    int i = blockIdx.x * blockDim.x + threadIdx.x;
    if (i >= n4) return;
    int r = i >> 8;
    int c = (i & 255) << 2;
    float4 v = in[i];
    __nv_bfloat16 h0 = __float2bfloat16(v.x), h1 = __float2bfloat16(v.y);
    __nv_bfloat16 h2 = __float2bfloat16(v.z), h3 = __float2bfloat16(v.w);
    __nv_bfloat16 l0 = __float2bfloat16(v.x - __bfloat162float(h0));
    __nv_bfloat16 l1 = __float2bfloat16(v.y - __bfloat162float(h1));
    __nv_bfloat16 l2 = __float2bfloat16(v.z - __bfloat162float(h2));
    __nv_bfloat16 l3 = __float2bfloat16(v.w - __bfloat162float(h3));
    __nv_bfloat162* oh = reinterpret_cast<__nv_bfloat162*>(out + (size_t)r * K2_ + c);
    __nv_bfloat162* ol = reinterpret_cast<__nv_bfloat162*>(out + (size_t)r * K2_ + 1024 + c);
    oh[0] = __nv_bfloat162(h0, h1); oh[1] = __nv_bfloat162(h2, h3);
    ol[0] = __nv_bfloat162(l0, l1); ol[1] = __nv_bfloat162(l2, l3);
}

// ---------------- HMMA bf16 GEMM, 3-term split precision ----------------
// CTA 128x256, BK=64, 3-stage cp.async, warp tile 64x64 (2x4 warps).
#define STAGE_BYTES 49152
#define GSMEM_SZ (3 * STAGE_BYTES)

template <bool BIAS>
__global__ __launch_bounds__(256, 1) void gemm_mma(
    const __nv_bfloat16* __restrict__ A, const __nv_bfloat16* __restrict__ Bw,
    const float* __restrict__ bias, float* __restrict__ C)
{
    extern __shared__ char smem[];
    const uint32_t sb = smem_u32(smem);
    const int tid = threadIdx.x, lane = tid & 31, wid = tid >> 5;
    const int wm = wid & 1, wn = wid >> 1;                 // 2 x 4 warp grid (64x64 tiles)
    const size_t bm = (size_t)blockIdx.y * 128;
    const size_t bn = (size_t)blockIdx.x * 256;

    const int lrow = tid >> 3;                              // 0..31
    const __nv_bfloat16* Ag = A + (bm + lrow) * K2_ + (tid & 7) * 8;
    const __nv_bfloat16* Bg = Bw + (bn + lrow) * K2_ + (tid & 7) * 8;
    const uint32_t ldOff = swz((uint32_t)(lrow * 128 + (tid & 7) * 16));

    const int qrow = lane & 15;
    const uint32_t khalf = (uint32_t)((lane >> 4) << 4);
    const uint32_t axor = (uint32_t)((qrow & 7) << 4);

    float acc[4][8][4];
#pragma unroll
    for (int mf = 0; mf < 4; mf++)
#pragma unroll
        for (int nf = 0; nf < 8; nf++)
#pragma unroll
            for (int j = 0; j < 4; j++) acc[mf][nf][j] = 0.f;

    auto kA = [](int i) { return (i < 32 ? i : i - 32) * 64; };
    auto kB = [](int i) { return (i < 16 ? i : i - 16) * 64; };

    auto issue = [&](int s, int i) {
        uint32_t ad = sb + s * STAGE_BYTES + ldOff;
        uint32_t bd = ad + 16384;
        const __nv_bfloat16* ag = Ag + kA(i);
        const __nv_bfloat16* bg = Bg + kB(i);
#pragma unroll
        for (int t = 0; t < 4; t++)
            cpasync16(ad + t * 4096, ag + (size_t)t * 32 * K2_);
#pragma unroll
        for (int t = 0; t < 8; t++)
            cpasync16(bd + t * 4096, bg + (size_t)t * 32 * K2_);
        asm volatile("cp.async.commit_group;");
    };

    issue(0, 0);
    issue(1, 1);

    for (int i = 0; i < NCHUNK; i++) {
        asm volatile("cp.async.wait_group 1;");
        __syncthreads();
        if (i + 2 < NCHUNK) issue((i + 2) % 3, i + 2);

        const uint32_t Ab = sb + (i % 3) * STAGE_BYTES;
        const uint32_t Bb = Ab + 16384;
#pragma unroll
        for (int ks = 0; ks < 4; ks++) {
            const uint32_t kb = (uint32_t)(ks * 32) + khalf;
            uint32_t af[4][4];
#pragma unroll
            for (int mf = 0; mf < 4; mf++)
                ldsm4(af[mf], Ab + (uint32_t)((wm * 64 + mf * 16 + qrow) * 128) + (kb ^ axor));
#pragma unroll
            for (int np = 0; np < 4; np++) {
                uint32_t r[4];
                ldsm4(r, Bb + (uint32_t)((wn * 64 + np * 16 + qrow) * 128) + (kb ^ axor));
#pragma unroll
                for (int mf = 0; mf < 4; mf++) {
                    mma16816(acc[mf][2 * np + 0], af[mf], r[0], r[2]);
                    mma16816(acc[mf][2 * np + 1], af[mf], r[1], r[3]);
                }
            }
        }
    }

    // epilogue
#pragma unroll
    for (int mf = 0; mf < 4; mf++) {
        const size_t row0 = bm + wm * 64 + mf * 16 + (lane >> 2);
#pragma unroll
        for (int nf = 0; nf < 8; nf++) {
            const int col = (int)bn + wn * 64 + nf * 8 + (lane & 3) * 2;
            float bx = 0.f, by = 0.f;
            if (BIAS) { bx = bias[col]; by = bias[col + 1]; }
            *reinterpret_cast<float2*>(C + row0 * C_ + col) =
                make_float2(acc[mf][nf][0] + bx, acc[mf][nf][1] + by);
            *reinterpret_cast<float2*>(C + (row0 + 8) * C_ + col) =
                make_float2(acc[mf][nf][2] + bx, acc[mf][nf][3] + by);
        }
    }
}

// ---------------- attention stage 1: partial S over one n-chunk ----------------
// grid 512: blockIdx.x = ((b*16+h)*4 + ch). Accumulates S[d][e] over 1024 tokens.
__global__ __launch_bounds__(256) void attn_s(const float* __restrict__ qkv,
                                              float* __restrict__ SP)
{
    __shared__ float Qs[64][64];
    __shared__ float Ks[64][68];
    const int tid = threadIdx.x;
    const int tx = tid & 15, ty = tid >> 4;
    const int bh = blockIdx.x >> 2, ch = blockIdx.x & 3;
    const int b = bh >> 4, h = bh & 15;
    const float* Q  = qkv + (size_t)b * (N_ * C_) + h * 64;
    const float* Kp = qkv + (size_t)(B_ + b) * (N_ * C_) + h * 64;
    const int nbase = ch * 1024;

    unsigned long long s2[4][2];
#pragma unroll
    for (int i = 0; i < 4; i++) { s2[i][0] = 0ull; s2[i][1] = 0ull; }

    for (int n0 = 0; n0 < 1024; n0 += 64) {
#pragma unroll
        for (int t = 0; t < 4; t++) {
            int fid = tid + t * 256;
            int nl  = fid >> 4;
            int c4  = (fid & 15) << 2;
            *reinterpret_cast<float4*>(&Qs[nl][c4]) =
                *reinterpret_cast<const float4*>(Q + (size_t)(nbase + n0 + nl) * C_ + c4);
            *reinterpret_cast<float4*>(&Ks[nl][c4]) =
                *reinterpret_cast<const float4*>(Kp + (size_t)(nbase + n0 + nl) * C_ + c4);
        }
        __syncthreads();
#pragma unroll 8
        for (int nl = 0; nl < 64; nl++) {
            float4 a  = *reinterpret_cast<const float4*>(&Qs[nl][tx * 4]);
            float4 bk = *reinterpret_cast<const float4*>(&Ks[nl][ty * 4]);
            unsigned long long e0 = pk2(bk.x, bk.y), e1 = pk2(bk.z, bk.w);
            float av[4] = {a.x, a.y, a.z, a.w};
#pragma unroll
            for (int i = 0; i < 4; i++) {
                unsigned long long ad = pk2(av[i], av[i]);
                fma2(s2[i][0], ad, e0);
                fma2(s2[i][1], ad, e1);
            }
        }
        __syncthreads();
    }

    float* sp = SP + (size_t)blockIdx.x * 4096;
#pragma unroll
    for (int i = 0; i < 4; i++) {
        float2 u0 = upk2(s2[i][0]), u1 = upk2(s2[i][1]);
        *reinterpret_cast<float4*>(sp + (tx * 4 + i) * 64 + ty * 4) =
            make_float4(u0.x, u0.y, u1.x, u1.y);
    }
}

// ---------------- attention stage 2: reduce partials + softmax ----------------
// grid 128 = (b,h). Row-wise softmax over e.
__global__ __launch_bounds__(256) void attn_sm(const float* __restrict__ SP,
                                               float* __restrict__ P)
{
    const int bh = blockIdx.x;
    const int warp = threadIdx.x >> 5, lane = threadIdx.x & 31;
    const float* sp = SP + (size_t)bh * 4 * 4096;
    float* p = P + (size_t)bh * 4096;
    for (int r = warp; r < 64; r += 8) {
        float v0 = 0.f, v1 = 0.f;
#pragma unroll
        for (int ch = 0; ch < 4; ch++) {
            v0 += sp[ch * 4096 + r * 64 + lane];
            v1 += sp[ch * 4096 + r * 64 + lane + 32];
        }
        v0 *= SCALE_; v1 *= SCALE_;
        float m = fmaxf(v0, v1);
#pragma unroll
        for (int off = 16; off; off >>= 1) m = fmaxf(m, __shfl_xor_sync(0xffffffffu, m, off));
        float e0 = expf(v0 - m), e1 = expf(v1 - m);
        float ssum = e0 + e1;
#pragma unroll
        for (int off = 16; off; off >>= 1) ssum += __shfl_xor_sync(0xffffffffu, ssum, off);
        float inv = 1.0f / ssum;
        p[r * 64 + lane] = e0 * inv;
        p[r * 64 + lane + 32] = e1 * inv;
    }
}

// ---------------- attention stage 3: O-chunk = P * V-chunk, write split bf16 ----------------
// grid 512: blockIdx.x = ((b*16+h)*4 + ch). Output row = b*4096 + d*64 + h*4 + ch, col = n%1024.
__global__ __launch_bounds__(256) void attn_pv(const float* __restrict__ qkv,
                                               const float* __restrict__ P,
                                               __nv_bfloat16* __restrict__ O2)
{
    __shared__ float Qs[64][64];   // P
    __shared__ float Ks[64][68];   // V^T tile
    const int tid = threadIdx.x;
    const int tx = tid & 15, ty = tid >> 4;
    const int bh = blockIdx.x >> 2, ch = blockIdx.x & 3;
    const int b = bh >> 4, h = bh & 15;
    const float* V = qkv + (size_t)(2 * B_ + b) * (N_ * C_) + h * 64;
    const int nbase = ch * 1024;

    // load P into smem
    {
        const float4* ps = reinterpret_cast<const float4*>(P + (size_t)bh * 4096);
#pragma unroll
        for (int t = 0; t < 4; t++) {
            int fid = tid + t * 256;
            *reinterpret_cast<float4*>(&Qs[fid >> 4][(fid & 15) << 2]) = ps[fid];
        }
    }
    __syncthreads();

    for (int n0 = 0; n0 < 1024; n0 += 64) {
#pragma unroll
        for (int t = 0; t < 4; t++) {
            int fid = tid + t * 256;
            int nl  = fid >> 4;
            int e4  = (fid & 15) << 2;
            float4 v = *reinterpret_cast<const float4*>(V + (size_t)(nbase + n0 + nl) * C_ + e4);
            Ks[e4 + 0][nl] = v.x; Ks[e4 + 1][nl] = v.y;
            Ks[e4 + 2][nl] = v.z; Ks[e4 + 3][nl] = v.w;
        }
        __syncthreads();
        unsigned long long o2a[4][2];
#pragma unroll
        for (int i = 0; i < 4; i++) { o2a[i][0] = 0ull; o2a[i][1] = 0ull; }
#pragma unroll 4
        for (int e = 0; e < 64; e += 4) {
            float4 p0 = *reinterpret_cast<const float4*>(&Qs[ty * 4 + 0][e]);
            float4 p1 = *reinterpret_cast<const float4*>(&Qs[ty * 4 + 1][e]);
            float4 p2 = *reinterpret_cast<const float4*>(&Qs[ty * 4 + 2][e]);
            float4 p3 = *reinterpret_cast<const float4*>(&Qs[ty * 4 + 3][e]);
            float4 v0 = *reinterpret_cast<const float4*>(&Ks[e + 0][tx * 4]);
            float4 v1 = *reinterpret_cast<const float4*>(&Ks[e + 1][tx * 4]);
            float4 v2 = *reinterpret_cast<const float4*>(&Ks[e + 2][tx * 4]);
            float4 v3 = *reinterpret_cast<const float4*>(&Ks[e + 3][tx * 4]);
            unsigned long long vq[4][2] = {
                {pk2(v0.x, v0.y), pk2(v0.z, v0.w)},
                {pk2(v1.x, v1.y), pk2(v1.z, v1.w)},
                {pk2(v2.x, v2.y), pk2(v2.z, v2.w)},
                {pk2(v3.x, v3.y), pk2(v3.z, v3.w)}};
            float pr[4][4] = {{p0.x, p0.y, p0.z, p0.w},
                              {p1.x, p1.y, p1.z, p1.w},
                              {p2.x, p2.y, p2.z, p2.w},
                              {p3.x, p3.y, p3.z, p3.w}};
#pragma unroll
            for (int i = 0; i < 4; i++) {
#pragma unroll
                for (int q = 0; q < 4; q++) {
                    unsigned long long pd = pk2(pr[i][q], pr[i][q]);
                    fma2(o2a[i][0], pd, vq[q][0]);
                    fma2(o2a[i][1], pd, vq[q][1]);
                }
            }
        }
        __syncthreads();
#pragma unroll
        for (int i = 0; i < 4; i++) {
            int d = ty * 4 + i;
            size_t row = (size_t)b * 4096 + (size_t)d * 64 + h * 4 + ch;
            int col = n0 + tx * 4;
            float2 u0 = upk2(o2a[i][0]), u1 = upk2(o2a[i][1]);
            float vv[4] = {u0.x, u0.y, u1.x, u1.y};
            __nv_bfloat16 hi[4], lo[4];
#pragma unroll
            for (int j = 0; j < 4; j++) {
                hi[j] = __float2bfloat16(vv[j]);
                lo[j] = __float2bfloat16(vv[j] - __bfloat162float(hi[j]));
            }
            *reinterpret_cast<uint2*>(O2 + row * K2_ + col) = *reinterpret_cast<uint2*>(hi);
            *reinterpret_cast<uint2*>(O2 + row * K2_ + 1024 + col) = *reinterpret_cast<uint2*>(lo);
        }
    }
}

extern "C" void kernel_launch(void* const* d_in, const int* in_sizes, int n_in,
                              void* d_out, int out_size)
{
    const float* x  = (const float*)d_in[0];
    const float* Wq = (const float*)d_in[1];
    const float* Wk = (const float*)d_in[2];
    const float* Wv = (const float*)d_in[3];
    const float* Wp = (const float*)d_in[4];
    const float* bp = (const float*)d_in[5];
    float* out = (float*)d_out;

    __nv_bfloat16 *x2 = nullptr, *w2 = nullptr, *o2 = nullptr;
    float *qkv = nullptr, *sp = nullptr, *p = nullptr;
    cudaGetSymbolAddress((void**)&x2, g_x2);
    cudaGetSymbolAddress((void**)&w2, g_w2);
    cudaGetSymbolAddress((void**)&qkv, g_qkv);
    cudaGetSymbolAddress((void**)&sp, g_sp);
    cudaGetSymbolAddress((void**)&p, g_p);
    cudaGetSymbolAddress((void**)&o2, g_o2);

    cudaFuncSetAttribute(gemm_mma<false>, cudaFuncAttributeMaxDynamicSharedMemorySize, GSMEM_SZ);
    cudaFuncSetAttribute(gemm_mma<true>,  cudaFuncAttributeMaxDynamicSharedMemorySize, GSMEM_SZ);

    const size_t wStride = (size_t)C_ * K2_;

    split_kernel<<<(M_ * C_ / 4 + 255) / 256, 256>>>((const float4*)x, x2, M_ * C_ / 4);
    split_kernel<<<(C_ * C_ / 4 + 255) / 256, 256>>>((const float4*)Wq, w2 + 0 * wStride, C_ * C_ / 4);
    split_kernel<<<(C_ * C_ / 4 + 255) / 256, 256>>>((const float4*)Wk, w2 + 1 * wStride, C_ * C_ / 4);
    split_kernel<<<(C_ * C_ / 4 + 255) / 256, 256>>>((const float4*)Wv, w2 + 2 * wStride, C_ * C_ / 4);
    split_kernel<<<(C_ * C_ / 4 + 255) / 256, 256>>>((const float4*)Wp, w2 + 3 * wStride, C_ * C_ / 4);

    dim3 grid(C_ / 256, M_ / 128);
    gemm_mma<false><<<grid, 256, GSMEM_SZ>>>(x2, w2 + 0 * wStride, nullptr, qkv);
    gemm_mma<false><<<grid, 256, GSMEM_SZ>>>(x2, w2 + 1 * wStride, nullptr, qkv + (size_t)M_ * C_);
    gemm_mma<false><<<grid, 256, GSMEM_SZ>>>(x2, w2 + 2 * wStride, nullptr, qkv + (size_t)2 * M_ * C_);

    attn_s <<<512, 256>>>(qkv, sp);
    attn_sm<<<128, 256>>>(sp, p);
    attn_pv<<<512, 256>>>(qkv, p, o2);

    gemm_mma<true><<<grid, 256, GSMEM_SZ>>>(o2, w2 + 3 * wStride, bp, out);
}

// round 7
// speedup vs baseline: 2.8190x; 1.3811x over previous
#include <cuda_runtime.h>
#include <cuda_bf16.h>
#include <cstdint>

#define B_ 8
#define N_ 4096
#define C_ 1024
#define H_ 16
#define SCALE_ 0.125f
#define M_ (B_ * N_)          // 32768 rows
#define K2_ 2048              // stored split K for 1024-wide operands

// ---------------- scratch ----------------
__device__ __align__(16) __nv_bfloat16 g_x2[(size_t)M_ * K2_];          // x split (hi|lo)
__device__ __align__(16) __nv_bfloat16 g_xt2[(size_t)B_ * C_ * 8192];   // x^T split per b: [c][hi n | lo n]
__device__ __align__(16) __nv_bfloat16 g_w2[3][(size_t)C_ * K2_];       // Wq, Wv, Wp split
__device__ float g_G[(size_t)B_ * C_ * C_];                             // Gram X^T X per b
__device__ __align__(16) __nv_bfloat16 g_g2[(size_t)B_ * C_ * K2_];     // G split
__device__ float g_T[(size_t)B_ * C_ * C_];                             // T = Wq G per b
__device__ float g_v[(size_t)M_ * C_];                                  // V = X Wv^T
__device__ float g_p[(size_t)128 * 4096];                               // softmaxed P
__device__ __align__(16) __nv_bfloat16 g_o2[(size_t)M_ * K2_];          // attn out split

// ---------------- helpers ----------------
__device__ __forceinline__ uint32_t smem_u32(const void* p) {
    uint32_t a;
    asm("{ .reg .u64 t; cvta.to.shared.u64 t, %1; cvt.u32.u64 %0, t; }" : "=r"(a) : "l"(p));
    return a;
}
__device__ __forceinline__ uint32_t swz(uint32_t off) {
    return off ^ ((off >> 3) & 0x70);
}
__device__ __forceinline__ void ldsm4(uint32_t* r, uint32_t addr) {
    asm volatile("ldmatrix.sync.aligned.m8n8.x4.shared.b16 {%0,%1,%2,%3}, [%4];"
                 : "=r"(r[0]), "=r"(r[1]), "=r"(r[2]), "=r"(r[3]) : "r"(addr));
}
__device__ __forceinline__ void mma16816(float* d, const uint32_t* a, uint32_t b0, uint32_t b1) {
    asm volatile("mma.sync.aligned.m16n8k16.row.col.f32.bf16.bf16.f32 "
                 "{%0,%1,%2,%3}, {%4,%5,%6,%7}, {%8,%9}, {%0,%1,%2,%3};"
                 : "+f"(d[0]), "+f"(d[1]), "+f"(d[2]), "+f"(d[3])
                 : "r"(a[0]), "r"(a[1]), "r"(a[2]), "r"(a[3]), "r"(b0), "r"(b1));
}
__device__ __forceinline__ void cpasync16(uint32_t dst, const void* src) {
    asm volatile("cp.async.cg.shared.global [%0], [%1], 16;" :: "r"(dst), "l"(src));
}
__device__ __forceinline__ unsigned long long pk2(float x, float y) {
    unsigned long long r;
    asm("mov.b64 %0, {%1, %2};" : "=l"(r)
        : "r"(__float_as_uint(x)), "r"(__float_as_uint(y)));
    return r;
}
__device__ __forceinline__ void fma2(unsigned long long& c, unsigned long long a,
                                     unsigned long long b) {
    asm("fma.rn.f32x2 %0, %1, %2, %0;" : "+l"(c) : "l"(a), "l"(b));
}
__device__ __forceinline__ float2 upk2(unsigned long long v) {
    unsigned int lo, hi;
    asm("mov.b64 {%0, %1}, %2;" : "=r"(lo), "=r"(hi) : "l"(v));
    return make_float2(__uint_as_float(lo), __uint_as_float(hi));
}

// ---------------- split fp32 -> [hi | lo] bf16 (rows of 1024) ----------------
__global__ void split_kernel(const float4* __restrict__ in, __nv_bfloat16* __restrict__ out,
                             int n4) {
    int i = blockIdx.x * blockDim.x + threadIdx.x;
    if (i >= n4) return;
    int r = i >> 8;
    int c = (i & 255) << 2;
    float4 v = in[i];
    __nv_bfloat16 h0 = __float2bfloat16(v.x), h1 = __float2bfloat16(v.y);
    __nv_bfloat16 h2 = __float2bfloat16(v.z), h3 = __float2bfloat16(v.w);
    __nv_bfloat16 l0 = __float2bfloat16(v.x - __bfloat162float(h0));
    __nv_bfloat16 l1 = __float2bfloat16(v.y - __bfloat162float(h1));
    __nv_bfloat16 l2 = __float2bfloat16(v.z - __bfloat162float(h2));
    __nv_bfloat16 l3 = __float2bfloat16(v.w - __bfloat162float(h3));
    __nv_bfloat162* oh = reinterpret_cast<__nv_bfloat162*>(out + (size_t)r * K2_ + c);
    __nv_bfloat162* ol = reinterpret_cast<__nv_bfloat162*>(out + (size_t)r * K2_ + 1024 + c);
    oh[0] = __nv_bfloat162(h0, h1); oh[1] = __nv_bfloat162(h2, h3);
    ol[0] = __nv_bfloat162(l0, l1); ol[1] = __nv_bfloat162(l2, l3);
}

// ---------------- transpose-split: X[b][n][c] -> xt2[b][c][hi n | lo n] ----------------
__global__ void tsplit_x(const float* __restrict__ x, __nv_bfloat16* __restrict__ xt) {
    __shared__ float tile[32][33];
    const int b = blockIdx.z;
    const int n0 = blockIdx.x * 32, c0 = blockIdx.y * 32;
    const int txx = threadIdx.x, tyy = threadIdx.y;
    const float* xb = x + ((size_t)b * 4096 + n0) * 1024 + c0;
#pragma unroll
    for (int k = 0; k < 4; k++)
        tile[tyy + k * 8][txx] = xb[(size_t)(tyy + k * 8) * 1024 + txx];
    __syncthreads();
    __nv_bfloat16* xo = xt + (size_t)b * C_ * 8192;
#pragma unroll
    for (int k = 0; k < 4; k++) {
        int c = c0 + tyy + k * 8;
        int n = n0 + txx;
        float v = tile[txx][tyy + k * 8];
        __nv_bfloat16 hi = __float2bfloat16(v);
        __nv_bfloat16 lo = __float2bfloat16(v - __bfloat162float(hi));
        xo[(size_t)c * 8192 + n] = hi;
        xo[(size_t)c * 8192 + 4096 + n] = lo;
    }
}

// ---------------- mirror (lower->full) + split G ----------------
__global__ void splitG(const float* __restrict__ G, __nv_bfloat16* __restrict__ g2) {
    size_t i = (size_t)blockIdx.x * 256 + threadIdx.x;   // 8*1024*256 quads
    int z = (int)(i >> 18);
    int rem = (int)(i & 262143);
    int rb = rem >> 8;
    int c4 = (rem & 255) << 2;
    const float* Gz = G + ((size_t)z << 20);
    float v[4];
    if ((rb >> 7) >= (c4 >> 7)) {
        float4 t = *reinterpret_cast<const float4*>(Gz + (size_t)rb * 1024 + c4);
        v[0] = t.x; v[1] = t.y; v[2] = t.z; v[3] = t.w;
    } else {
#pragma unroll
        for (int j = 0; j < 4; j++) v[j] = Gz[(size_t)(c4 + j) * 1024 + rb];
    }
    __nv_bfloat16 hi[4], lo[4];
#pragma unroll
    for (int j = 0; j < 4; j++) {
        hi[j] = __float2bfloat16(v[j]);
        lo[j] = __float2bfloat16(v[j] - __bfloat162float(hi[j]));
    }
    __nv_bfloat16* o = g2 + (size_t)z * C_ * K2_ + (size_t)rb * K2_;
    *reinterpret_cast<uint2*>(o + c4) = *reinterpret_cast<uint2*>(hi);
    *reinterpret_cast<uint2*>(o + 1024 + c4) = *reinterpret_cast<uint2*>(lo);
}

// ---------------- HMMA split-precision GEMM (R5-proven core, parameterized) ----------------
// C[z][m][n(1024 wide)] = A[z rows m][*] . B[z rows n][*]^T  over split chunks.
// CMAP 0: K=1024 op (48 chunks, RS=2048). CMAP 1: Gram K=4096 (192 chunks, RS=8192).
// SYM: grid.x=36 triangular tile pairs (A==B), batched over z.
#define STAGE_BYTES 32768
#define GSMEM_SZ (3 * STAGE_BYTES)

template <int CMAP, int RS, int NCH, bool SYM, bool BIAS>
__global__ __launch_bounds__(256, 2) void gemm_mma(
    const __nv_bfloat16* __restrict__ A, const __nv_bfloat16* __restrict__ Bw,
    const float* __restrict__ bias, float* __restrict__ C,
    int aBatchRows, int bBatchRows, size_t cBatch)
{
    extern __shared__ char smem[];
    const uint32_t sb = smem_u32(smem);
    const int tid = threadIdx.x, lane = tid & 31, wid = tid >> 5;
    const int wm = wid & 3, wn = wid >> 2;                 // 4 x 2 warp grid (32x64)
    const int z = blockIdx.z;
    size_t bm, bn;
    if (SYM) {
        int idx = blockIdx.x;
        int ti = (int)floorf((sqrtf(8.f * idx + 1.f) - 1.f) * 0.5f);
        while ((ti + 1) * (ti + 2) / 2 <= idx) ti++;
        while (ti * (ti + 1) / 2 > idx) ti--;
        int tj = idx - ti * (ti + 1) / 2;
        bm = (size_t)ti * 128; bn = (size_t)tj * 128;
    } else {
        bm = (size_t)blockIdx.y * 128;
        bn = (size_t)blockIdx.x * 128;
    }
    const __nv_bfloat16* Az = A + (size_t)z * aBatchRows * RS;
    const __nv_bfloat16* Bz = Bw + (size_t)z * bBatchRows * RS;
    float* Cz = C + (size_t)z * cBatch;

    const int lrow = tid >> 3;
    const __nv_bfloat16* Ag = Az + (bm + lrow) * RS + (tid & 7) * 8;
    const __nv_bfloat16* Bg = Bz + (bn + lrow) * RS + (tid & 7) * 8;
    const uint32_t aOff = swz((uint32_t)(lrow * 128 + (tid & 7) * 16));

    const int qrow = lane & 15;
    const uint32_t khalf = (uint32_t)((lane >> 4) << 4);
    const uint32_t axor = (uint32_t)((qrow & 7) << 4);

    float acc[2][8][4];
#pragma unroll
    for (int mf = 0; mf < 2; mf++)
#pragma unroll
        for (int nf = 0; nf < 8; nf++)
#pragma unroll
            for (int j = 0; j < 4; j++) acc[mf][nf][j] = 0.f;

    auto kA = [](int i) -> int {
        if (CMAP == 0) return (i < 32 ? i : i - 32) * 64;
        int t = i >> 6, j = i & 63;
        return j * 64 + (t == 1 ? 4096 : 0);
    };
    auto kB = [](int i) -> int {
        if (CMAP == 0) return (i < 16 ? i : i - 16) * 64;
        int t = i >> 6, j = i & 63;
        return j * 64 + (t == 2 ? 4096 : 0);
    };

    auto issue = [&](int s, int i) {
        uint32_t ad = sb + s * STAGE_BYTES + aOff;
        uint32_t bd = ad + 16384;
        const __nv_bfloat16* ag = Ag + kA(i);
        const __nv_bfloat16* bg = Bg + kB(i);
#pragma unroll
        for (int t = 0; t < 4; t++) {
            cpasync16(ad + t * 4096, ag + (size_t)t * 32 * RS);
            cpasync16(bd + t * 4096, bg + (size_t)t * 32 * RS);
        }
        asm volatile("cp.async.commit_group;");
    };

    issue(0, 0);
    issue(1, 1);

    for (int i = 0; i < NCH; i++) {
        asm volatile("cp.async.wait_group 1;");
        __syncthreads();
        if (i + 2 < NCH) issue((i + 2) % 3, i + 2);

        const uint32_t Ab = sb + (i % 3) * STAGE_BYTES;
        const uint32_t Bb = Ab + 16384;
#pragma unroll
        for (int ks = 0; ks < 4; ks++) {
            const uint32_t kb = (uint32_t)(ks * 32) + khalf;
            uint32_t af[2][4];
#pragma unroll
            for (int mf = 0; mf < 2; mf++)
                ldsm4(af[mf], Ab + (uint32_t)((wm * 32 + mf * 16 + qrow) * 128) + (kb ^ axor));
#pragma unroll
            for (int np = 0; np < 4; np++) {
                uint32_t r[4];
                ldsm4(r, Bb + (uint32_t)((wn * 64 + np * 16 + qrow) * 128) + (kb ^ axor));
#pragma unroll
                for (int mf = 0; mf < 2; mf++) {
                    mma16816(acc[mf][2 * np + 0], af[mf], r[0], r[2]);
                    mma16816(acc[mf][2 * np + 1], af[mf], r[1], r[3]);
                }
            }
        }
    }

#pragma unroll
    for (int mf = 0; mf < 2; mf++) {
        const size_t row0 = bm + wm * 32 + mf * 16 + (lane >> 2);
#pragma unroll
        for (int nf = 0; nf < 8; nf++) {
            const int col = (int)bn + wn * 64 + nf * 8 + (lane & 3) * 2;
            float bx = 0.f, by = 0.f;
            if (BIAS) { bx = bias[col]; by = bias[col + 1]; }
            *reinterpret_cast<float2*>(Cz + row0 * C_ + col) =
                make_float2(acc[mf][nf][0] + bx, acc[mf][nf][1] + by);
            *reinterpret_cast<float2*>(Cz + (row0 + 8) * C_ + col) =
                make_float2(acc[mf][nf][2] + bx, acc[mf][nf][3] + by);
        }
    }
}

// ---------------- attn_mid: S = T_h Wk_h^T (fp32), softmax -> P. 128 blocks (b,h) ----------------
__global__ __launch_bounds__(256) void attn_mid(const float* __restrict__ T,
                                                const float* __restrict__ Wk,
                                                float* __restrict__ P)
{
    __shared__ float Ts[64][68];
    __shared__ float Wks[64][68];
    const int tid = threadIdx.x;
    const int tx = tid & 15, ty = tid >> 4;
    const int bh = blockIdx.x, b = bh >> 4, h = bh & 15;
    const float* Tb  = T + ((size_t)b << 20) + (size_t)(h * 64) * 1024;
    const float* Wkb = Wk + (size_t)(h * 64) * 1024;

    unsigned long long s2[4][2];
#pragma unroll
    for (int i = 0; i < 4; i++) { s2[i][0] = 0ull; s2[i][1] = 0ull; }

    for (int c0 = 0; c0 < 1024; c0 += 64) {
#pragma unroll
        for (int t = 0; t < 4; t++) {
            int fid = tid + t * 256;
            int r  = fid >> 4;
            int c4 = (fid & 15) << 2;
            float4 a = *reinterpret_cast<const float4*>(Tb + (size_t)r * 1024 + c0 + c4);
            Ts[c4 + 0][r] = a.x; Ts[c4 + 1][r] = a.y;
            Ts[c4 + 2][r] = a.z; Ts[c4 + 3][r] = a.w;
            float4 w = *reinterpret_cast<const float4*>(Wkb + (size_t)r * 1024 + c0 + c4);
            Wks[c4 + 0][r] = w.x; Wks[c4 + 1][r] = w.y;
            Wks[c4 + 2][r] = w.z; Wks[c4 + 3][r] = w.w;
        }
        __syncthreads();
#pragma unroll 8
        for (int cc = 0; cc < 64; cc++) {
            float4 a  = *reinterpret_cast<const float4*>(&Ts[cc][tx * 4]);
            float4 bk = *reinterpret_cast<const float4*>(&Wks[cc][ty * 4]);
            unsigned long long e0 = pk2(bk.x, bk.y), e1 = pk2(bk.z, bk.w);
            float av[4] = {a.x, a.y, a.z, a.w};
#pragma unroll
            for (int i = 0; i < 4; i++) {
                unsigned long long ad = pk2(av[i], av[i]);
                fma2(s2[i][0], ad, e0);
                fma2(s2[i][1], ad, e1);
            }
        }
        __syncthreads();
    }

    // scaled S into flat smem [64][64]
    float* Ss = &Ts[0][0];
#pragma unroll
    for (int i = 0; i < 4; i++) {
        float2 u0 = upk2(s2[i][0]), u1 = upk2(s2[i][1]);
        *reinterpret_cast<float4*>(Ss + (tx * 4 + i) * 64 + ty * 4) =
            make_float4(u0.x * SCALE_, u0.y * SCALE_, u1.x * SCALE_, u1.y * SCALE_);
    }
    __syncthreads();

    {
        int warp = tid >> 5, lane = tid & 31;
        float* p = P + (size_t)bh * 4096;
        for (int r = warp; r < 64; r += 8) {
            float v0 = Ss[r * 64 + lane], v1 = Ss[r * 64 + lane + 32];
            float m = fmaxf(v0, v1);
#pragma unroll
            for (int off = 16; off; off >>= 1) m = fmaxf(m, __shfl_xor_sync(0xffffffffu, m, off));
            float e0 = expf(v0 - m), e1 = expf(v1 - m);
            float ssum = e0 + e1;
#pragma unroll
            for (int off = 16; off; off >>= 1) ssum += __shfl_xor_sync(0xffffffffu, ssum, off);
            float inv = 1.0f / ssum;
            p[r * 64 + lane] = e0 * inv;
            p[r * 64 + lane + 32] = e1 * inv;
        }
    }
}

// ---------------- attn_pv: O-chunk = P * V-chunk, write split bf16 (verified R6) ----------------
__global__ __launch_bounds__(256) void attn_pv(const float* __restrict__ Vbuf,
                                               const float* __restrict__ P,
                                               __nv_bfloat16* __restrict__ O2)
{
    __shared__ float Qs[64][64];
    __shared__ float Ks[64][68];
    const int tid = threadIdx.x;
    const int tx = tid & 15, ty = tid >> 4;
    const int bh = blockIdx.x >> 2, ch = blockIdx.x & 3;
    const int b = bh >> 4, h = bh & 15;
    const float* V = Vbuf + (size_t)b * (N_ * C_) + h * 64;
    const int nbase = ch * 1024;

    {
        const float4* ps = reinterpret_cast<const float4*>(P + (size_t)bh * 4096);
#pragma unroll
        for (int t = 0; t < 4; t++) {
            int fid = tid + t * 256;
            *reinterpret_cast<float4*>(&Qs[fid >> 4][(fid & 15) << 2]) = ps[fid];
        }
    }
    __syncthreads();

    for (int n0 = 0; n0 < 1024; n0 += 64) {
#pragma unroll
        for (int t = 0; t < 4; t++) {
            int fid = tid + t * 256;
            int nl  = fid >> 4;
            int e4  = (fid & 15) << 2;
            float4 v = *reinterpret_cast<const float4*>(V + (size_t)(nbase + n0 + nl) * C_ + e4);
            Ks[e4 + 0][nl] = v.x; Ks[e4 + 1][nl] = v.y;
            Ks[e4 + 2][nl] = v.z; Ks[e4 + 3][nl] = v.w;
        }
        __syncthreads();
        unsigned long long o2a[4][2];
#pragma unroll
        for (int i = 0; i < 4; i++) { o2a[i][0] = 0ull; o2a[i][1] = 0ull; }
#pragma unroll 4
        for (int e = 0; e < 64; e += 4) {
            float4 p0 = *reinterpret_cast<const float4*>(&Qs[ty * 4 + 0][e]);
            float4 p1 = *reinterpret_cast<const float4*>(&Qs[ty * 4 + 1][e]);
            float4 p2 = *reinterpret_cast<const float4*>(&Qs[ty * 4 + 2][e]);
            float4 p3 = *reinterpret_cast<const float4*>(&Qs[ty * 4 + 3][e]);
            float4 v0 = *reinterpret_cast<const float4*>(&Ks[e + 0][tx * 4]);
            float4 v1 = *reinterpret_cast<const float4*>(&Ks[e + 1][tx * 4]);
            float4 v2 = *reinterpret_cast<const float4*>(&Ks[e + 2][tx * 4]);
            float4 v3 = *reinterpret_cast<const float4*>(&Ks[e + 3][tx * 4]);
            unsigned long long vq[4][2] = {
                {pk2(v0.x, v0.y), pk2(v0.z, v0.w)},
                {pk2(v1.x, v1.y), pk2(v1.z, v1.w)},
                {pk2(v2.x, v2.y), pk2(v2.z, v2.w)},
                {pk2(v3.x, v3.y), pk2(v3.z, v3.w)}};
            float pr[4][4] = {{p0.x, p0.y, p0.z, p0.w},
                              {p1.x, p1.y, p1.z, p1.w},
                              {p2.x, p2.y, p2.z, p2.w},
                              {p3.x, p3.y, p3.z, p3.w}};
#pragma unroll
            for (int i = 0; i < 4; i++) {
#pragma unroll
                for (int q = 0; q < 4; q++) {
                    unsigned long long pd = pk2(pr[i][q], pr[i][q]);
                    fma2(o2a[i][0], pd, vq[q][0]);
                    fma2(o2a[i][1], pd, vq[q][1]);
                }
            }
        }
        __syncthreads();
#pragma unroll
        for (int i = 0; i < 4; i++) {
            int d = ty * 4 + i;
            size_t row = (size_t)b * 4096 + (size_t)d * 64 + h * 4 + ch;
            int col = n0 + tx * 4;
            float2 u0 = upk2(o2a[i][0]), u1 = upk2(o2a[i][1]);
            float vv[4] = {u0.x, u0.y, u1.x, u1.y};
            __nv_bfloat16 hi[4], lo[4];
#pragma unroll
            for (int j = 0; j < 4; j++) {
                hi[j] = __float2bfloat16(vv[j]);
                lo[j] = __float2bfloat16(vv[j] - __bfloat162float(hi[j]));
            }
            *reinterpret_cast<uint2*>(O2 + row * K2_ + col) = *reinterpret_cast<uint2*>(hi);
            *reinterpret_cast<uint2*>(O2 + row * K2_ + 1024 + col) = *reinterpret_cast<uint2*>(lo);
        }
    }
}

extern "C" void kernel_launch(void* const* d_in, const int* in_sizes, int n_in,
                              void* d_out, int out_size)
{
    const float* x  = (const float*)d_in[0];
    const float* Wq = (const float*)d_in[1];
    const float* Wk = (const float*)d_in[2];
    const float* Wv = (const float*)d_in[3];
    const float* Wp = (const float*)d_in[4];
    const float* bp = (const float*)d_in[5];
    float* out = (float*)d_out;

    __nv_bfloat16 *x2, *xt2, *w2, *g2, *o2;
    float *G, *T, *v, *p;
    cudaGetSymbolAddress((void**)&x2, g_x2);
    cudaGetSymbolAddress((void**)&xt2, g_xt2);
    cudaGetSymbolAddress((void**)&w2, g_w2);
    cudaGetSymbolAddress((void**)&G, g_G);
    cudaGetSymbolAddress((void**)&g2, g_g2);
    cudaGetSymbolAddress((void**)&T, g_T);
    cudaGetSymbolAddress((void**)&v, g_v);
    cudaGetSymbolAddress((void**)&p, g_p);
    cudaGetSymbolAddress((void**)&o2, g_o2);

    auto* kV = gemm_mma<0, 2048, 48, false, false>;
    auto* kF = gemm_mma<0, 2048, 48, false, true>;
    auto* kG = gemm_mma<1, 8192, 192, true, false>;
    cudaFuncSetAttribute(kV, cudaFuncAttributeMaxDynamicSharedMemorySize, GSMEM_SZ);
    cudaFuncSetAttribute(kF, cudaFuncAttributeMaxDynamicSharedMemorySize, GSMEM_SZ);
    cudaFuncSetAttribute(kG, cudaFuncAttributeMaxDynamicSharedMemorySize, GSMEM_SZ);

    const size_t wStride = (size_t)C_ * K2_;
    __nv_bfloat16* wq2 = w2;
    __nv_bfloat16* wv2 = w2 + wStride;
    __nv_bfloat16* wp2 = w2 + 2 * wStride;

    // prep
    split_kernel<<<(M_ * C_ / 4 + 255) / 256, 256>>>((const float4*)x, x2, M_ * C_ / 4);
    tsplit_x<<<dim3(128, 32, 8), dim3(32, 8)>>>(x, xt2);
    split_kernel<<<(C_ * C_ / 4 + 255) / 256, 256>>>((const float4*)Wq, wq2, C_ * C_ / 4);
    split_kernel<<<(C_ * C_ / 4 + 255) / 256, 256>>>((const float4*)Wv, wv2, C_ * C_ / 4);
    split_kernel<<<(C_ * C_ / 4 + 255) / 256, 256>>>((const float4*)Wp, wp2, C_ * C_ / 4);

    // Gram: G_b = X_b^T X_b (lower tiles), mirror+split
    kG<<<dim3(36, 1, 8), 256, GSMEM_SZ>>>(xt2, xt2, nullptr, G, C_, C_, (size_t)C_ * C_);
    splitG<<<8192, 256>>>(G, g2);

    // T_b = Wq * G_b (G symmetric -> NT form works)
    kV<<<dim3(8, 8, 8), 256, GSMEM_SZ>>>(wq2, g2, nullptr, T, 0, C_, (size_t)C_ * C_);

    // V = X Wv^T
    kV<<<dim3(8, 256, 1), 256, GSMEM_SZ>>>(x2, wv2, nullptr, v, 0, 0, 0);

    // S + softmax -> P ; then O = P V (split output)
    attn_mid<<<128, 256>>>(T, Wk, p);
    attn_pv<<<512, 256>>>(v, p, o2);

    // out = O' Wp^T + bp
    kF<<<dim3(8, 256, 1), 256, GSMEM_SZ>>>(o2, wp2, bp, out, 0, 0, 0);
}

// round 8
// speedup vs baseline: 2.8827x; 1.0226x over previous
#include <cuda_runtime.h>
#include <cuda_bf16.h>
#include <cstdint>

#define B_ 8
#define N_ 4096
#define C_ 1024
#define H_ 16
#define SCALE_ 0.125f
#define M_ (B_ * N_)          // 32768 rows
#define K2_ 2048              // stored split K for 1024-wide operands

// ---------------- scratch ----------------
__device__ __align__(16) __nv_bfloat16 g_x2[(size_t)M_ * K2_];          // x split (hi|lo)
__device__ __align__(16) __nv_bfloat16 g_xt2[(size_t)B_ * C_ * 8192];   // x^T split per b: [c][hi n | lo n]
__device__ __align__(16) __nv_bfloat16 g_w2[3][(size_t)C_ * K2_];       // Wq, Wv, Wp split
__device__ __align__(16) __nv_bfloat16 g_g2[(size_t)B_ * C_ * K2_];     // G split (written by Gram epilogue)
__device__ float g_T[(size_t)B_ * C_ * C_];                             // T = Wq G per b
__device__ float g_v[(size_t)M_ * C_];                                  // V = X Wv^T
__device__ float g_p[(size_t)128 * 4096];                               // softmaxed P
__device__ __align__(16) __nv_bfloat16 g_o2[(size_t)M_ * K2_];          // attn out split

// ---------------- helpers ----------------
__device__ __forceinline__ uint32_t smem_u32(const void* p) {
    uint32_t a;
    asm("{ .reg .u64 t; cvta.to.shared.u64 t, %1; cvt.u32.u64 %0, t; }" : "=r"(a) : "l"(p));
    return a;
}
__device__ __forceinline__ uint32_t swz(uint32_t off) {
    return off ^ ((off >> 3) & 0x70);
}
__device__ __forceinline__ void ldsm4(uint32_t* r, uint32_t addr) {
    asm volatile("ldmatrix.sync.aligned.m8n8.x4.shared.b16 {%0,%1,%2,%3}, [%4];"
                 : "=r"(r[0]), "=r"(r[1]), "=r"(r[2]), "=r"(r[3]) : "r"(addr));
}
__device__ __forceinline__ void mma16816(float* d, const uint32_t* a, uint32_t b0, uint32_t b1) {
    asm volatile("mma.sync.aligned.m16n8k16.row.col.f32.bf16.bf16.f32 "
                 "{%0,%1,%2,%3}, {%4,%5,%6,%7}, {%8,%9}, {%0,%1,%2,%3};"
                 : "+f"(d[0]), "+f"(d[1]), "+f"(d[2]), "+f"(d[3])
                 : "r"(a[0]), "r"(a[1]), "r"(a[2]), "r"(a[3]), "r"(b0), "r"(b1));
}
__device__ __forceinline__ void cpasync16(uint32_t dst, const void* src) {
    asm volatile("cp.async.cg.shared.global [%0], [%1], 16;" :: "r"(dst), "l"(src));
}
__device__ __forceinline__ unsigned long long pk2(float x, float y) {
    unsigned long long r;
    asm("mov.b64 %0, {%1, %2};" : "=l"(r)
        : "r"(__float_as_uint(x)), "r"(__float_as_uint(y)));
    return r;
}
__device__ __forceinline__ void fma2(unsigned long long& c, unsigned long long a,
                                     unsigned long long b) {
    asm("fma.rn.f32x2 %0, %1, %2, %0;" : "+l"(c) : "l"(a), "l"(b));
}
__device__ __forceinline__ float2 upk2(unsigned long long v) {
    unsigned int lo, hi;
    asm("mov.b64 {%0, %1}, %2;" : "=r"(lo), "=r"(hi) : "l"(v));
    return make_float2(__uint_as_float(lo), __uint_as_float(hi));
}
__device__ __forceinline__ void split1(float v, __nv_bfloat16& hi, __nv_bfloat16& lo) {
    hi = __float2bfloat16(v);
    lo = __float2bfloat16(v - __bfloat162float(hi));
}

// ---------------- split fp32 -> [hi | lo] bf16 (rows of 1024) ----------------
__global__ void split_kernel(const float4* __restrict__ in, __nv_bfloat16* __restrict__ out,
                             int n4) {
    int i = blockIdx.x * blockDim.x + threadIdx.x;
    if (i >= n4) return;
    int r = i >> 8;
    int c = (i & 255) << 2;
    float4 v = in[i];
    __nv_bfloat16 hi[4], lo[4];
    split1(v.x, hi[0], lo[0]); split1(v.y, hi[1], lo[1]);
    split1(v.z, hi[2], lo[2]); split1(v.w, hi[3], lo[3]);
    *reinterpret_cast<uint2*>(out + (size_t)r * K2_ + c) = *reinterpret_cast<uint2*>(hi);
    *reinterpret_cast<uint2*>(out + (size_t)r * K2_ + 1024 + c) = *reinterpret_cast<uint2*>(lo);
}

// ---------------- fused x prep: x2 (row split) + xt2 (transpose split) ----------------
__global__ void prep_x(const float* __restrict__ x, __nv_bfloat16* __restrict__ x2,
                       __nv_bfloat16* __restrict__ xt) {
    __shared__ float tile[32][33];
    const int b = blockIdx.z;
    const int n0 = blockIdx.x * 32, c0 = blockIdx.y * 32;
    const int txx = threadIdx.x, tyy = threadIdx.y;
    const float* xb = x + ((size_t)b * 4096 + n0) * 1024 + c0;
    __nv_bfloat16* x2b = x2 + ((size_t)b * 4096 + n0) * (size_t)K2_ + c0;
#pragma unroll
    for (int k = 0; k < 4; k++) {
        int nr = tyy + k * 8;
        float v = xb[(size_t)nr * 1024 + txx];
        tile[nr][txx] = v;
        __nv_bfloat16 hi, lo;
        split1(v, hi, lo);
        x2b[(size_t)nr * K2_ + txx] = hi;
        x2b[(size_t)nr * K2_ + 1024 + txx] = lo;
    }
    __syncthreads();
    __nv_bfloat16* xo = xt + (size_t)b * C_ * 8192;
#pragma unroll
    for (int k = 0; k < 4; k++) {
        int c = c0 + tyy + k * 8;
        int n = n0 + txx;
        float v = tile[txx][tyy + k * 8];
        __nv_bfloat16 hi, lo;
        split1(v, hi, lo);
        xo[(size_t)c * 8192 + n] = hi;
        xo[(size_t)c * 8192 + 4096 + n] = lo;
    }
}

// ---------------- HMMA split-precision GEMM (R5-proven core, parameterized) ----------------
// CMAP 0: K=1024 op (48 chunks, RS=2048). CMAP 1: Gram K=4096 (192 chunks, RS=8192).
// SYM: triangular tile grid (A==B). GOUT: epilogue writes split-bf16 (with mirror).
#define STAGE_BYTES 32768
#define GSMEM_SZ (3 * STAGE_BYTES)

template <int CMAP, int RS, int NCH, bool SYM, bool BIAS, bool GOUT>
__global__ __launch_bounds__(256, 2) void gemm_mma(
    const __nv_bfloat16* __restrict__ A, const __nv_bfloat16* __restrict__ Bw,
    const float* __restrict__ bias, void* __restrict__ Cptr,
    int aBatchRows, int bBatchRows, size_t cBatch)
{
    extern __shared__ char smem[];
    const uint32_t sb = smem_u32(smem);
    const int tid = threadIdx.x, lane = tid & 31, wid = tid >> 5;
    const int wm = wid & 3, wn = wid >> 2;                 // 4 x 2 warp grid (32x64)
    const int z = blockIdx.z;
    size_t bm, bn;
    if (SYM) {
        int idx = blockIdx.x;
        int ti = (int)floorf((sqrtf(8.f * idx + 1.f) - 1.f) * 0.5f);
        while ((ti + 1) * (ti + 2) / 2 <= idx) ti++;
        while (ti * (ti + 1) / 2 > idx) ti--;
        int tj = idx - ti * (ti + 1) / 2;
        bm = (size_t)ti * 128; bn = (size_t)tj * 128;
    } else {
        bm = (size_t)blockIdx.y * 128;
        bn = (size_t)blockIdx.x * 128;
    }
    const __nv_bfloat16* Az = A + (size_t)z * aBatchRows * RS;
    const __nv_bfloat16* Bz = Bw + (size_t)z * bBatchRows * RS;

    const int lrow = tid >> 3;
    const __nv_bfloat16* Ag = Az + (bm + lrow) * RS + (tid & 7) * 8;
    const __nv_bfloat16* Bg = Bz + (bn + lrow) * RS + (tid & 7) * 8;
    const uint32_t aOff = swz((uint32_t)(lrow * 128 + (tid & 7) * 16));

    const int qrow = lane & 15;
    const uint32_t khalf = (uint32_t)((lane >> 4) << 4);
    const uint32_t axor = (uint32_t)((qrow & 7) << 4);

    float acc[2][8][4];
#pragma unroll
    for (int mf = 0; mf < 2; mf++)
#pragma unroll
        for (int nf = 0; nf < 8; nf++)
#pragma unroll
            for (int j = 0; j < 4; j++) acc[mf][nf][j] = 0.f;

    auto kA = [](int i) -> int {
        if (CMAP == 0) return (i < 32 ? i : i - 32) * 64;
        int t = i >> 6, j = i & 63;
        return j * 64 + (t == 1 ? 4096 : 0);
    };
    auto kB = [](int i) -> int {
        if (CMAP == 0) return (i < 16 ? i : i - 16) * 64;
        int t = i >> 6, j = i & 63;
        return j * 64 + (t == 2 ? 4096 : 0);
    };

    auto issue = [&](int s, int i) {
        uint32_t ad = sb + s * STAGE_BYTES + aOff;
        uint32_t bd = ad + 16384;
        const __nv_bfloat16* ag = Ag + kA(i);
        const __nv_bfloat16* bg = Bg + kB(i);
#pragma unroll
        for (int t = 0; t < 4; t++) {
            cpasync16(ad + t * 4096, ag + (size_t)t * 32 * RS);
            cpasync16(bd + t * 4096, bg + (size_t)t * 32 * RS);
        }
        asm volatile("cp.async.commit_group;");
    };

    issue(0, 0);
    issue(1, 1);

    for (int i = 0; i < NCH; i++) {
        asm volatile("cp.async.wait_group 1;");
        __syncthreads();
        if (i + 2 < NCH) issue((i + 2) % 3, i + 2);

        const uint32_t Ab = sb + (i % 3) * STAGE_BYTES;
        const uint32_t Bb = Ab + 16384;
#pragma unroll
        for (int ks = 0; ks < 4; ks++) {
            const uint32_t kb = (uint32_t)(ks * 32) + khalf;
            uint32_t af[2][4];
#pragma unroll
            for (int mf = 0; mf < 2; mf++)
                ldsm4(af[mf], Ab + (uint32_t)((wm * 32 + mf * 16 + qrow) * 128) + (kb ^ axor));
#pragma unroll
            for (int np = 0; np < 4; np++) {
                uint32_t r[4];
                ldsm4(r, Bb + (uint32_t)((wn * 64 + np * 16 + qrow) * 128) + (kb ^ axor));
#pragma unroll
                for (int mf = 0; mf < 2; mf++) {
                    mma16816(acc[mf][2 * np + 0], af[mf], r[0], r[2]);
                    mma16816(acc[mf][2 * np + 1], af[mf], r[1], r[3]);
                }
            }
        }
    }

    if (GOUT) {
        // stage fp32 tile in smem [128][129], then write split bf16 (+mirror)
        __syncthreads();
        float* st = reinterpret_cast<float*>(smem);
#pragma unroll
        for (int mf = 0; mf < 2; mf++) {
            int r0 = wm * 32 + mf * 16 + (lane >> 2);
#pragma unroll
            for (int nf = 0; nf < 8; nf++) {
                int c = wn * 64 + nf * 8 + (lane & 3) * 2;
                st[r0 * 129 + c]       = acc[mf][nf][0];
                st[r0 * 129 + c + 1]   = acc[mf][nf][1];
                st[(r0 + 8) * 129 + c]     = acc[mf][nf][2];
                st[(r0 + 8) * 129 + c + 1] = acc[mf][nf][3];
            }
        }
        __syncthreads();
        __nv_bfloat16* g2o = reinterpret_cast<__nv_bfloat16*>(Cptr) + (size_t)z * C_ * K2_;
        const int r = tid >> 1, cbase = (tid & 1) * 64;
#pragma unroll
        for (int g = 0; g < 8; g++) {
            __nv_bfloat16 hi[8], lo[8];
#pragma unroll
            for (int j = 0; j < 8; j++)
                split1(st[r * 129 + cbase + g * 8 + j], hi[j], lo[j]);
            size_t base = (bm + r) * (size_t)K2_ + bn + cbase + g * 8;
            *reinterpret_cast<uint4*>(g2o + base) = *reinterpret_cast<uint4*>(hi);
            *reinterpret_cast<uint4*>(g2o + base + 1024) = *reinterpret_cast<uint4*>(lo);
        }
        if (bm != bn) {
#pragma unroll
            for (int g = 0; g < 8; g++) {
                __nv_bfloat16 hi[8], lo[8];
#pragma unroll
                for (int j = 0; j < 8; j++)
                    split1(st[(cbase + g * 8 + j) * 129 + r], hi[j], lo[j]);
                size_t base = (bn + r) * (size_t)K2_ + bm + cbase + g * 8;
                *reinterpret_cast<uint4*>(g2o + base) = *reinterpret_cast<uint4*>(hi);
                *reinterpret_cast<uint4*>(g2o + base + 1024) = *reinterpret_cast<uint4*>(lo);
            }
        }
    } else {
        float* Cz = reinterpret_cast<float*>(Cptr) + (size_t)z * cBatch;
#pragma unroll
        for (int mf = 0; mf < 2; mf++) {
            const size_t row0 = bm + wm * 32 + mf * 16 + (lane >> 2);
#pragma unroll
            for (int nf = 0; nf < 8; nf++) {
                const int col = (int)bn + wn * 64 + nf * 8 + (lane & 3) * 2;
                float bx = 0.f, by = 0.f;
                if (BIAS) { bx = bias[col]; by = bias[col + 1]; }
                *reinterpret_cast<float2*>(Cz + row0 * C_ + col) =
                    make_float2(acc[mf][nf][0] + bx, acc[mf][nf][1] + by);
                *reinterpret_cast<float2*>(Cz + (row0 + 8) * C_ + col) =
                    make_float2(acc[mf][nf][2] + bx, acc[mf][nf][3] + by);
            }
        }
    }
}

// ---------------- attn_mid: S = T_h Wk_h^T (fp32), softmax -> P. 128 blocks (b,h) ----------------
__global__ __launch_bounds__(256) void attn_mid(const float* __restrict__ T,
                                                const float* __restrict__ Wk,
                                                float* __restrict__ P)
{
    __shared__ float Ts[64][68];
    __shared__ float Wks[64][68];
    const int tid = threadIdx.x;
    const int tx = tid & 15, ty = tid >> 4;
    const int bh = blockIdx.x, b = bh >> 4, h = bh & 15;
    const float* Tb  = T + ((size_t)b << 20) + (size_t)(h * 64) * 1024;
    const float* Wkb = Wk + (size_t)(h * 64) * 1024;

    unsigned long long s2[4][2];
#pragma unroll
    for (int i = 0; i < 4; i++) { s2[i][0] = 0ull; s2[i][1] = 0ull; }

    for (int c0 = 0; c0 < 1024; c0 += 64) {
#pragma unroll
        for (int t = 0; t < 4; t++) {
            int fid = tid + t * 256;
            int r  = fid >> 4;
            int c4 = (fid & 15) << 2;
            float4 a = *reinterpret_cast<const float4*>(Tb + (size_t)r * 1024 + c0 + c4);
            Ts[c4 + 0][r] = a.x; Ts[c4 + 1][r] = a.y;
            Ts[c4 + 2][r] = a.z; Ts[c4 + 3][r] = a.w;
            float4 w = *reinterpret_cast<const float4*>(Wkb + (size_t)r * 1024 + c0 + c4);
            Wks[c4 + 0][r] = w.x; Wks[c4 + 1][r] = w.y;
            Wks[c4 + 2][r] = w.z; Wks[c4 + 3][r] = w.w;
        }
        __syncthreads();
#pragma unroll 8
        for (int cc = 0; cc < 64; cc++) {
            float4 a  = *reinterpret_cast<const float4*>(&Ts[cc][tx * 4]);
            float4 bk = *reinterpret_cast<const float4*>(&Wks[cc][ty * 4]);
            unsigned long long e0 = pk2(bk.x, bk.y), e1 = pk2(bk.z, bk.w);
            float av[4] = {a.x, a.y, a.z, a.w};
#pragma unroll
            for (int i = 0; i < 4; i++) {
                unsigned long long ad = pk2(av[i], av[i]);
                fma2(s2[i][0], ad, e0);
                fma2(s2[i][1], ad, e1);
            }
        }
        __syncthreads();
    }

    float* Ss = &Ts[0][0];
#pragma unroll
    for (int i = 0; i < 4; i++) {
        float2 u0 = upk2(s2[i][0]), u1 = upk2(s2[i][1]);
        *reinterpret_cast<float4*>(Ss + (tx * 4 + i) * 64 + ty * 4) =
            make_float4(u0.x * SCALE_, u0.y * SCALE_, u1.x * SCALE_, u1.y * SCALE_);
    }
    __syncthreads();

    {
        int warp = tid >> 5, lane = tid & 31;
        float* p = P + (size_t)bh * 4096;
        for (int r = warp; r < 64; r += 8) {
            float v0 = Ss[r * 64 + lane], v1 = Ss[r * 64 + lane + 32];
            float m = fmaxf(v0, v1);
#pragma unroll
            for (int off = 16; off; off >>= 1) m = fmaxf(m, __shfl_xor_sync(0xffffffffu, m, off));
            float e0 = expf(v0 - m), e1 = expf(v1 - m);
            float ssum = e0 + e1;
#pragma unroll
            for (int off = 16; off; off >>= 1) ssum += __shfl_xor_sync(0xffffffffu, ssum, off);
            float inv = 1.0f / ssum;
            p[r * 64 + lane] = e0 * inv;
            p[r * 64 + lane + 32] = e1 * inv;
        }
    }
}

// ---------------- attn_pv: O-chunk = P * V-chunk, write split bf16 ----------------
__global__ __launch_bounds__(256) void attn_pv(const float* __restrict__ Vbuf,
                                               const float* __restrict__ P,
                                               __nv_bfloat16* __restrict__ O2)
{
    __shared__ float Qs[64][64];
    __shared__ float Ks[64][68];
    const int tid = threadIdx.x;
    const int tx = tid & 15, ty = tid >> 4;
    const int bh = blockIdx.x >> 2, ch = blockIdx.x & 3;
    const int b = bh >> 4, h = bh & 15;
    const float* V = Vbuf + (size_t)b * (N_ * C_) + h * 64;
    const int nbase = ch * 1024;

    {
        const float4* ps = reinterpret_cast<const float4*>(P + (size_t)bh * 4096);
#pragma unroll
        for (int t = 0; t < 4; t++) {
            int fid = tid + t * 256;
            *reinterpret_cast<float4*>(&Qs[fid >> 4][(fid & 15) << 2]) = ps[fid];
        }
    }
    __syncthreads();

    for (int n0 = 0; n0 < 1024; n0 += 64) {
#pragma unroll
        for (int t = 0; t < 4; t++) {
            int fid = tid + t * 256;
            int nl  = fid >> 4;
            int e4  = (fid & 15) << 2;
            float4 v = *reinterpret_cast<const float4*>(V + (size_t)(nbase + n0 + nl) * C_ + e4);
            Ks[e4 + 0][nl] = v.x; Ks[e4 + 1][nl] = v.y;
            Ks[e4 + 2][nl] = v.z; Ks[e4 + 3][nl] = v.w;
        }
        __syncthreads();
        unsigned long long o2a[4][2];
#pragma unroll
        for (int i = 0; i < 4; i++) { o2a[i][0] = 0ull; o2a[i][1] = 0ull; }
#pragma unroll 4
        for (int e = 0; e < 64; e += 4) {
            float4 p0 = *reinterpret_cast<const float4*>(&Qs[ty * 4 + 0][e]);
            float4 p1 = *reinterpret_cast<const float4*>(&Qs[ty * 4 + 1][e]);
            float4 p2 = *reinterpret_cast<const float4*>(&Qs[ty * 4 + 2][e]);
            float4 p3 = *reinterpret_cast<const float4*>(&Qs[ty * 4 + 3][e]);
            float4 v0 = *reinterpret_cast<const float4*>(&Ks[e + 0][tx * 4]);
            float4 v1 = *reinterpret_cast<const float4*>(&Ks[e + 1][tx * 4]);
            float4 v2 = *reinterpret_cast<const float4*>(&Ks[e + 2][tx * 4]);
            float4 v3 = *reinterpret_cast<const float4*>(&Ks[e + 3][tx * 4]);
            unsigned long long vq[4][2] = {
                {pk2(v0.x, v0.y), pk2(v0.z, v0.w)},
                {pk2(v1.x, v1.y), pk2(v1.z, v1.w)},
                {pk2(v2.x, v2.y), pk2(v2.z, v2.w)},
                {pk2(v3.x, v3.y), pk2(v3.z, v3.w)}};
            float pr[4][4] = {{p0.x, p0.y, p0.z, p0.w},
                              {p1.x, p1.y, p1.z, p1.w},
                              {p2.x, p2.y, p2.z, p2.w},
                              {p3.x, p3.y, p3.z, p3.w}};
#pragma unroll
            for (int i = 0; i < 4; i++) {
#pragma unroll
                for (int q = 0; q < 4; q++) {
                    unsigned long long pd = pk2(pr[i][q], pr[i][q]);
                    fma2(o2a[i][0], pd, vq[q][0]);
                    fma2(o2a[i][1], pd, vq[q][1]);
                }
            }
        }
        __syncthreads();
#pragma unroll
        for (int i = 0; i < 4; i++) {
            int d = ty * 4 + i;
            size_t row = (size_t)b * 4096 + (size_t)d * 64 + h * 4 + ch;
            int col = n0 + tx * 4;
            float2 u0 = upk2(o2a[i][0]), u1 = upk2(o2a[i][1]);
            float vv[4] = {u0.x, u0.y, u1.x, u1.y};
            __nv_bfloat16 hi[4], lo[4];
#pragma unroll
            for (int j = 0; j < 4; j++) split1(vv[j], hi[j], lo[j]);
            *reinterpret_cast<uint2*>(O2 + row * K2_ + col) = *reinterpret_cast<uint2*>(hi);
            *reinterpret_cast<uint2*>(O2 + row * K2_ + 1024 + col) = *reinterpret_cast<uint2*>(lo);
        }
    }
}

extern "C" void kernel_launch(void* const* d_in, const int* in_sizes, int n_in,
                              void* d_out, int out_size)
{
    const float* x  = (const float*)d_in[0];
    const float* Wq = (const float*)d_in[1];
    const float* Wk = (const float*)d_in[2];
    const float* Wv = (const float*)d_in[3];
    const float* Wp = (const float*)d_in[4];
    const float* bp = (const float*)d_in[5];
    float* out = (float*)d_out;

    __nv_bfloat16 *x2, *xt2, *w2, *g2, *o2;
    float *T, *v, *p;
    cudaGetSymbolAddress((void**)&x2, g_x2);
    cudaGetSymbolAddress((void**)&xt2, g_xt2);
    cudaGetSymbolAddress((void**)&w2, g_w2);
    cudaGetSymbolAddress((void**)&g2, g_g2);
    cudaGetSymbolAddress((void**)&T, g_T);
    cudaGetSymbolAddress((void**)&v, g_v);
    cudaGetSymbolAddress((void**)&p, g_p);
    cudaGetSymbolAddress((void**)&o2, g_o2);

    auto* kV = gemm_mma<0, 2048, 48, false, false, false>;
    auto* kF = gemm_mma<0, 2048, 48, false, true, false>;
    auto* kG = gemm_mma<1, 8192, 192, true, false, true>;
    cudaFuncSetAttribute(kV, cudaFuncAttributeMaxDynamicSharedMemorySize, GSMEM_SZ);
    cudaFuncSetAttribute(kF, cudaFuncAttributeMaxDynamicSharedMemorySize, GSMEM_SZ);
    cudaFuncSetAttribute(kG, cudaFuncAttributeMaxDynamicSharedMemorySize, GSMEM_SZ);

    const size_t wStride = (size_t)C_ * K2_;
    __nv_bfloat16* wq2 = w2;
    __nv_bfloat16* wv2 = w2 + wStride;
    __nv_bfloat16* wp2 = w2 + 2 * wStride;

    // prep (launch 1-4)
    prep_x<<<dim3(128, 32, 8), dim3(32, 8)>>>(x, x2, xt2);
    split_kernel<<<(C_ * C_ / 4 + 255) / 256, 256>>>((const float4*)Wq, wq2, C_ * C_ / 4);
    split_kernel<<<(C_ * C_ / 4 + 255) / 256, 256>>>((const float4*)Wv, wv2, C_ * C_ / 4);
    split_kernel<<<(C_ * C_ / 4 + 255) / 256, 256>>>((const float4*)Wp, wp2, C_ * C_ / 4);

    // launch 5: Gram -> split g2 directly (with mirror)
    kG<<<dim3(36, 1, 8), 256, GSMEM_SZ>>>(xt2, xt2, nullptr, g2, C_, C_, 0);

    // launch 6: V = X Wv^T   (ncu -s 5 -c 1 captures this one)
    kV<<<dim3(8, 256, 1), 256, GSMEM_SZ>>>(x2, wv2, nullptr, v, 0, 0, 0);

    // T_b = Wq * G_b (G symmetric -> NT form)
    kV<<<dim3(8, 8, 8), 256, GSMEM_SZ>>>(wq2, g2, nullptr, T, 0, C_, (size_t)C_ * C_);

    // S + softmax -> P ; then O = P V (split output)
    attn_mid<<<128, 256>>>(T, Wk, p);
    attn_pv<<<512, 256>>>(v, p, o2);

    // out = O' Wp^T + bp
    kF<<<dim3(8, 256, 1), 256, GSMEM_SZ>>>(o2, wp2, bp, out, 0, 0, 0);
}

// round 9
// speedup vs baseline: 3.1367x; 1.0881x over previous
#include <cuda_runtime.h>
#include <cuda_bf16.h>
#include <cuda.h>
#include <cstdint>
#include <dlfcn.h>

#define B_ 8
#define N_ 4096
#define C_ 1024
#define H_ 16
#define SCALE_ 0.125f
#define M_ (B_ * N_)          // 32768 rows
#define K2_ 2048              // stored split K for 1024-wide operands

// ---------------- scratch ----------------
__device__ __align__(16) __nv_bfloat16 g_x2[(size_t)M_ * K2_];          // x split (hi|lo)
__device__ __align__(16) __nv_bfloat16 g_xt2[(size_t)B_ * C_ * 8192];   // x^T split per b
__device__ __align__(16) __nv_bfloat16 g_w2[3][(size_t)C_ * K2_];       // Wq, Wv, Wp split
__device__ __align__(16) __nv_bfloat16 g_g2[(size_t)B_ * C_ * K2_];     // G split
__device__ float g_T[(size_t)B_ * C_ * C_];                             // T = Wq G per b
__device__ float g_v[(size_t)M_ * C_];                                  // V = X Wv^T
__device__ float g_p[(size_t)128 * 4096];                               // softmaxed P
__device__ __align__(16) __nv_bfloat16 g_o2[(size_t)M_ * K2_];          // attn out split

// ---------------- helpers ----------------
__device__ __forceinline__ uint32_t smem_u32(const void* p) {
    uint32_t a;
    asm("{ .reg .u64 t; cvta.to.shared.u64 t, %1; cvt.u32.u64 %0, t; }" : "=r"(a) : "l"(p));
    return a;
}
__device__ __forceinline__ void ldsm4(uint32_t* r, uint32_t addr) {
    asm volatile("ldmatrix.sync.aligned.m8n8.x4.shared.b16 {%0,%1,%2,%3}, [%4];"
                 : "=r"(r[0]), "=r"(r[1]), "=r"(r[2]), "=r"(r[3]) : "r"(addr));
}
__device__ __forceinline__ void mma16816(float* d, const uint32_t* a, uint32_t b0, uint32_t b1) {
    asm volatile("mma.sync.aligned.m16n8k16.row.col.f32.bf16.bf16.f32 "
                 "{%0,%1,%2,%3}, {%4,%5,%6,%7}, {%8,%9}, {%0,%1,%2,%3};"
                 : "+f"(d[0]), "+f"(d[1]), "+f"(d[2]), "+f"(d[3])
                 : "r"(a[0]), "r"(a[1]), "r"(a[2]), "r"(a[3]), "r"(b0), "r"(b1));
}
__device__ __forceinline__ void mbar_init(uint32_t a, uint32_t cnt) {
    asm volatile("mbarrier.init.shared.b64 [%0], %1;" :: "r"(a), "r"(cnt) : "memory");
}
__device__ __forceinline__ void mbar_wait(uint32_t a, uint32_t parity) {
    asm volatile(
        "{\n\t.reg .pred P;\n\t"
        "W_%=:\n\t"
        "mbarrier.try_wait.parity.acquire.cta.shared::cta.b64 P, [%0], %1, 0x989680;\n\t"
        "@P bra D_%=;\n\t"
        "bra W_%=;\n\t"
        "D_%=:\n\t}"
        :: "r"(a), "r"(parity) : "memory");
}
__device__ __forceinline__ void tma2d(uint32_t smem, const CUtensorMap* tm,
                                      int cx, int cy, uint32_t mbar) {
    asm volatile("cp.async.bulk.tensor.2d.shared::cta.global.tile.mbarrier::complete_tx::bytes "
                 "[%0], [%1, {%2, %3}], [%4];"
                 :: "r"(smem), "l"(tm), "r"(cx), "r"(cy), "r"(mbar) : "memory");
}
__device__ __forceinline__ unsigned long long pk2(float x, float y) {
    unsigned long long r;
    asm("mov.b64 %0, {%1, %2};" : "=l"(r)
        : "r"(__float_as_uint(x)), "r"(__float_as_uint(y)));
    return r;
}
__device__ __forceinline__ void fma2(unsigned long long& c, unsigned long long a,
                                     unsigned long long b) {
    asm("fma.rn.f32x2 %0, %1, %2, %0;" : "+l"(c) : "l"(a), "l"(b));
}
__device__ __forceinline__ float2 upk2(unsigned long long v) {
    unsigned int lo, hi;
    asm("mov.b64 {%0, %1}, %2;" : "=r"(lo), "=r"(hi) : "l"(v));
    return make_float2(__uint_as_float(lo), __uint_as_float(hi));
}
__device__ __forceinline__ void split1(float v, __nv_bfloat16& hi, __nv_bfloat16& lo) {
    hi = __float2bfloat16(v);
    lo = __float2bfloat16(v - __bfloat162float(hi));
}

// ---------------- split fp32 -> [hi | lo] bf16 (rows of 1024) ----------------
__global__ void split_kernel(const float4* __restrict__ in, __nv_bfloat16* __restrict__ out,
                             int n4) {
    int i = blockIdx.x * blockDim.x + threadIdx.x;
    if (i >= n4) return;
    int r = i >> 8;
    int c = (i & 255) << 2;
    float4 v = in[i];
    __nv_bfloat16 hi[4], lo[4];
    split1(v.x, hi[0], lo[0]); split1(v.y, hi[1], lo[1]);
    split1(v.z, hi[2], lo[2]); split1(v.w, hi[3], lo[3]);
    *reinterpret_cast<uint2*>(out + (size_t)r * K2_ + c) = *reinterpret_cast<uint2*>(hi);
    *reinterpret_cast<uint2*>(out + (size_t)r * K2_ + 1024 + c) = *reinterpret_cast<uint2*>(lo);
}

// ---------------- fused x prep: x2 (row split) + xt2 (transpose split) ----------------
__global__ void prep_x(const float* __restrict__ x, __nv_bfloat16* __restrict__ x2,
                       __nv_bfloat16* __restrict__ xt) {
    __shared__ float tile[32][33];
    const int b = blockIdx.z;
    const int n0 = blockIdx.x * 32, c0 = blockIdx.y * 32;
    const int txx = threadIdx.x, tyy = threadIdx.y;
    const float* xb = x + ((size_t)b * 4096 + n0) * 1024 + c0;
    __nv_bfloat16* x2b = x2 + ((size_t)b * 4096 + n0) * (size_t)K2_ + c0;
#pragma unroll
    for (int k = 0; k < 4; k++) {
        int nr = tyy + k * 8;
        float v = xb[(size_t)nr * 1024 + txx];
        tile[nr][txx] = v;
        __nv_bfloat16 hi, lo;
        split1(v, hi, lo);
        x2b[(size_t)nr * K2_ + txx] = hi;
        x2b[(size_t)nr * K2_ + 1024 + txx] = lo;
    }
    __syncthreads();
    __nv_bfloat16* xo = xt + (size_t)b * C_ * 8192;
#pragma unroll
    for (int k = 0; k < 4; k++) {
        int c = c0 + tyy + k * 8;
        int n = n0 + txx;
        float v = tile[txx][tyy + k * 8];
        __nv_bfloat16 hi, lo;
        split1(v, hi, lo);
        xo[(size_t)c * 8192 + n] = hi;
        xo[(size_t)c * 8192 + 4096 + n] = lo;
    }
}

// ---------------- TMA HMMA split-precision GEMM ----------------
// CMAP 0: K=1024 op (48 chunks). CMAP 1: Gram K=4096 (192 chunks, cols=8192).
// SYM: triangular tile grid (A==B). GOUT: epilogue writes split-bf16 (+mirror).
#define STAGE_BYTES 32768
#define GSMEM_SZ (3 * STAGE_BYTES + 64)

template <int CMAP, int NCH, bool SYM, bool BIAS, bool GOUT>
__global__ __launch_bounds__(256, 2) void gemm_tma(
    const __grid_constant__ CUtensorMap tmA, const __grid_constant__ CUtensorMap tmB,
    const float* __restrict__ bias, void* __restrict__ Cptr,
    int aBatchRows, int bBatchRows, size_t cBatch)
{
    extern __shared__ char smem[];
    const uint32_t sb = smem_u32(smem);
    const uint32_t mbb = sb + 3 * STAGE_BYTES;
    const int tid = threadIdx.x, lane = tid & 31, wid = tid >> 5;
    const int wm = wid & 3, wn = wid >> 2;                 // 4 x 2 warp grid (32x64)
    const int z = blockIdx.z;
    int bm, bn;
    if (SYM) {
        int idx = blockIdx.x;
        int ti = (int)floorf((sqrtf(8.f * idx + 1.f) - 1.f) * 0.5f);
        while ((ti + 1) * (ti + 2) / 2 <= idx) ti++;
        while (ti * (ti + 1) / 2 > idx) ti--;
        int tj = idx - ti * (ti + 1) / 2;
        bm = ti * 128; bn = tj * 128;
    } else {
        bm = blockIdx.y * 128;
        bn = blockIdx.x * 128;
    }
    const int cyA = z * aBatchRows + bm;
    const int cyB = z * bBatchRows + bn;

    const int qrow = lane & 15;
    const uint32_t khalf = (uint32_t)((lane >> 4) << 4);
    const uint32_t axor = (uint32_t)((qrow & 7) << 4);

    float acc[2][8][4];
#pragma unroll
    for (int mf = 0; mf < 2; mf++)
#pragma unroll
        for (int nf = 0; nf < 8; nf++)
#pragma unroll
            for (int j = 0; j < 4; j++) acc[mf][nf][j] = 0.f;

    auto kA = [](int i) -> int {
        if (CMAP == 0) return (i < 32 ? i : i - 32) * 64;
        int t = i >> 6, j = i & 63;
        return j * 64 + (t == 1 ? 4096 : 0);
    };
    auto kB = [](int i) -> int {
        if (CMAP == 0) return (i < 16 ? i : i - 16) * 64;
        int t = i >> 6, j = i & 63;
        return j * 64 + (t == 2 ? 4096 : 0);
    };

    if (tid == 0) {
#pragma unroll
        for (int s = 0; s < 3; s++) mbar_init(mbb + s * 8, 1);
    }
    __syncthreads();

    auto issue = [&](int i) {
        uint32_t st = sb + (uint32_t)(i % 3) * STAGE_BYTES;
        uint32_t mb = mbb + (uint32_t)(i % 3) * 8;
        asm volatile("mbarrier.arrive.expect_tx.shared.b64 _, [%0], %1;"
                     :: "r"(mb), "r"(32768u) : "memory");
        tma2d(st, &tmA, kA(i), cyA, mb);
        tma2d(st + 16384, &tmB, kB(i), cyB, mb);
    };

    if (tid == 0) { issue(0); issue(1); }

    for (int i = 0; i < NCH; i++) {
        mbar_wait(mbb + (i % 3) * 8, (i / 3) & 1);
        __syncthreads();                      // all threads saw data; compute(i-1) done
        if (tid == 0 && i + 2 < NCH) issue(i + 2);

        const uint32_t Ab = sb + (uint32_t)(i % 3) * STAGE_BYTES;
        const uint32_t Bb = Ab + 16384;
#pragma unroll
        for (int ks = 0; ks < 4; ks++) {
            const uint32_t kb = (uint32_t)(ks * 32) + khalf;
            uint32_t af[2][4];
#pragma unroll
            for (int mf = 0; mf < 2; mf++)
                ldsm4(af[mf], Ab + (uint32_t)((wm * 32 + mf * 16 + qrow) * 128) + (kb ^ axor));
#pragma unroll
            for (int np = 0; np < 4; np++) {
                uint32_t r[4];
                ldsm4(r, Bb + (uint32_t)((wn * 64 + np * 16 + qrow) * 128) + (kb ^ axor));
#pragma unroll
                for (int mf = 0; mf < 2; mf++) {
                    mma16816(acc[mf][2 * np + 0], af[mf], r[0], r[2]);
                    mma16816(acc[mf][2 * np + 1], af[mf], r[1], r[3]);
                }
            }
        }
    }

    if (GOUT) {
        __syncthreads();
        float* st = reinterpret_cast<float*>(smem);
#pragma unroll
        for (int mf = 0; mf < 2; mf++) {
            int r0 = wm * 32 + mf * 16 + (lane >> 2);
#pragma unroll
            for (int nf = 0; nf < 8; nf++) {
                int c = wn * 64 + nf * 8 + (lane & 3) * 2;
                st[r0 * 129 + c]       = acc[mf][nf][0];
                st[r0 * 129 + c + 1]   = acc[mf][nf][1];
                st[(r0 + 8) * 129 + c]     = acc[mf][nf][2];
                st[(r0 + 8) * 129 + c + 1] = acc[mf][nf][3];
            }
        }
        __syncthreads();
        __nv_bfloat16* g2o = reinterpret_cast<__nv_bfloat16*>(Cptr) + (size_t)z * C_ * K2_;
        const int r = tid >> 1, cbase = (tid & 1) * 64;
#pragma unroll
        for (int g = 0; g < 8; g++) {
            __nv_bfloat16 hi[8], lo[8];
#pragma unroll
            for (int j = 0; j < 8; j++)
                split1(st[r * 129 + cbase + g * 8 + j], hi[j], lo[j]);
            size_t base = (size_t)(bm + r) * K2_ + bn + cbase + g * 8;
            *reinterpret_cast<uint4*>(g2o + base) = *reinterpret_cast<uint4*>(hi);
            *reinterpret_cast<uint4*>(g2o + base + 1024) = *reinterpret_cast<uint4*>(lo);
        }
        if (bm != bn) {
#pragma unroll
            for (int g = 0; g < 8; g++) {
                __nv_bfloat16 hi[8], lo[8];
#pragma unroll
                for (int j = 0; j < 8; j++)
                    split1(st[(cbase + g * 8 + j) * 129 + r], hi[j], lo[j]);
                size_t base = (size_t)(bn + r) * K2_ + bm + cbase + g * 8;
                *reinterpret_cast<uint4*>(g2o + base) = *reinterpret_cast<uint4*>(hi);
                *reinterpret_cast<uint4*>(g2o + base + 1024) = *reinterpret_cast<uint4*>(lo);
            }
        }
    } else {
        float* Cz = reinterpret_cast<float*>(Cptr) + (size_t)z * cBatch;
#pragma unroll
        for (int mf = 0; mf < 2; mf++) {
            const size_t row0 = (size_t)bm + wm * 32 + mf * 16 + (lane >> 2);
#pragma unroll
            for (int nf = 0; nf < 8; nf++) {
                const int col = bn + wn * 64 + nf * 8 + (lane & 3) * 2;
                float bx = 0.f, by = 0.f;
                if (BIAS) { bx = bias[col]; by = bias[col + 1]; }
                *reinterpret_cast<float2*>(Cz + row0 * C_ + col) =
                    make_float2(acc[mf][nf][0] + bx, acc[mf][nf][1] + by);
                *reinterpret_cast<float2*>(Cz + (row0 + 8) * C_ + col) =
                    make_float2(acc[mf][nf][2] + bx, acc[mf][nf][3] + by);
            }
        }
    }
}

// ---------------- attn_mid: S = T_h Wk_h^T (fp32), softmax -> P ----------------
__global__ __launch_bounds__(256) void attn_mid(const float* __restrict__ T,
                                                const float* __restrict__ Wk,
                                                float* __restrict__ P)
{
    __shared__ float Ts[64][68];
    __shared__ float Wks[64][68];
    const int tid = threadIdx.x;
    const int tx = tid & 15, ty = tid >> 4;
    const int bh = blockIdx.x, b = bh >> 4, h = bh & 15;
    const float* Tb  = T + ((size_t)b << 20) + (size_t)(h * 64) * 1024;
    const float* Wkb = Wk + (size_t)(h * 64) * 1024;

    unsigned long long s2[4][2];
#pragma unroll
    for (int i = 0; i < 4; i++) { s2[i][0] = 0ull; s2[i][1] = 0ull; }

    for (int c0 = 0; c0 < 1024; c0 += 64) {
#pragma unroll
        for (int t = 0; t < 4; t++) {
            int fid = tid + t * 256;
            int r  = fid >> 4;
            int c4 = (fid & 15) << 2;
            float4 a = *reinterpret_cast<const float4*>(Tb + (size_t)r * 1024 + c0 + c4);
            Ts[c4 + 0][r] = a.x; Ts[c4 + 1][r] = a.y;
            Ts[c4 + 2][r] = a.z; Ts[c4 + 3][r] = a.w;
            float4 w = *reinterpret_cast<const float4*>(Wkb + (size_t)r * 1024 + c0 + c4);
            Wks[c4 + 0][r] = w.x; Wks[c4 + 1][r] = w.y;
            Wks[c4 + 2][r] = w.z; Wks[c4 + 3][r] = w.w;
        }
        __syncthreads();
#pragma unroll 8
        for (int cc = 0; cc < 64; cc++) {
            float4 a  = *reinterpret_cast<const float4*>(&Ts[cc][tx * 4]);
            float4 bk = *reinterpret_cast<const float4*>(&Wks[cc][ty * 4]);
            unsigned long long e0 = pk2(bk.x, bk.y), e1 = pk2(bk.z, bk.w);
            float av[4] = {a.x, a.y, a.z, a.w};
#pragma unroll
            for (int i = 0; i < 4; i++) {
                unsigned long long ad = pk2(av[i], av[i]);
                fma2(s2[i][0], ad, e0);
                fma2(s2[i][1], ad, e1);
            }
        }
        __syncthreads();
    }

    float* Ss = &Ts[0][0];
#pragma unroll
    for (int i = 0; i < 4; i++) {
        float2 u0 = upk2(s2[i][0]), u1 = upk2(s2[i][1]);
        *reinterpret_cast<float4*>(Ss + (tx * 4 + i) * 64 + ty * 4) =
            make_float4(u0.x * SCALE_, u0.y * SCALE_, u1.x * SCALE_, u1.y * SCALE_);
    }
    __syncthreads();

    {
        int warp = tid >> 5, lane = tid & 31;
        float* p = P + (size_t)bh * 4096;
        for (int r = warp; r < 64; r += 8) {
            float v0 = Ss[r * 64 + lane], v1 = Ss[r * 64 + lane + 32];
            float m = fmaxf(v0, v1);
#pragma unroll
            for (int off = 16; off; off >>= 1) m = fmaxf(m, __shfl_xor_sync(0xffffffffu, m, off));
            float e0 = expf(v0 - m), e1 = expf(v1 - m);
            float ssum = e0 + e1;
#pragma unroll
            for (int off = 16; off; off >>= 1) ssum += __shfl_xor_sync(0xffffffffu, ssum, off);
            float inv = 1.0f / ssum;
            p[r * 64 + lane] = e0 * inv;
            p[r * 64 + lane + 32] = e1 * inv;
        }
    }
}

// ---------------- attn_pv: O-chunk = P * V-chunk, write split bf16 ----------------
__global__ __launch_bounds__(256) void attn_pv(const float* __restrict__ Vbuf,
                                               const float* __restrict__ P,
                                               __nv_bfloat16* __restrict__ O2)
{
    __shared__ float Qs[64][64];
    __shared__ float Ks[64][68];
    const int tid = threadIdx.x;
    const int tx = tid & 15, ty = tid >> 4;
    const int bh = blockIdx.x >> 2, ch = blockIdx.x & 3;
    const int b = bh >> 4, h = bh & 15;
    const float* V = Vbuf + (size_t)b * (N_ * C_) + h * 64;
    const int nbase = ch * 1024;

    {
        const float4* ps = reinterpret_cast<const float4*>(P + (size_t)bh * 4096);
#pragma unroll
        for (int t = 0; t < 4; t++) {
            int fid = tid + t * 256;
            *reinterpret_cast<float4*>(&Qs[fid >> 4][(fid & 15) << 2]) = ps[fid];
        }
    }
    __syncthreads();

    for (int n0 = 0; n0 < 1024; n0 += 64) {
#pragma unroll
        for (int t = 0; t < 4; t++) {
            int fid = tid + t * 256;
            int nl  = fid >> 4;
            int e4  = (fid & 15) << 2;
            float4 v = *reinterpret_cast<const float4*>(V + (size_t)(nbase + n0 + nl) * C_ + e4);
            Ks[e4 + 0][nl] = v.x; Ks[e4 + 1][nl] = v.y;
            Ks[e4 + 2][nl] = v.z; Ks[e4 + 3][nl] = v.w;
        }
        __syncthreads();
        unsigned long long o2a[4][2];
#pragma unroll
        for (int i = 0; i < 4; i++) { o2a[i][0] = 0ull; o2a[i][1] = 0ull; }
#pragma unroll 4
        for (int e = 0; e < 64; e += 4) {
            float4 p0 = *reinterpret_cast<const float4*>(&Qs[ty * 4 + 0][e]);
            float4 p1 = *reinterpret_cast<const float4*>(&Qs[ty * 4 + 1][e]);
            float4 p2 = *reinterpret_cast<const float4*>(&Qs[ty * 4 + 2][e]);
            float4 p3 = *reinterpret_cast<const float4*>(&Qs[ty * 4 + 3][e]);
            float4 v0 = *reinterpret_cast<const float4*>(&Ks[e + 0][tx * 4]);
            float4 v1 = *reinterpret_cast<const float4*>(&Ks[e + 1][tx * 4]);
            float4 v2 = *reinterpret_cast<const float4*>(&Ks[e + 2][tx * 4]);
            float4 v3 = *reinterpret_cast<const float4*>(&Ks[e + 3][tx * 4]);
            unsigned long long vq[4][2] = {
                {pk2(v0.x, v0.y), pk2(v0.z, v0.w)},
                {pk2(v1.x, v1.y), pk2(v1.z, v1.w)},
                {pk2(v2.x, v2.y), pk2(v2.z, v2.w)},
                {pk2(v3.x, v3.y), pk2(v3.z, v3.w)}};
            float pr[4][4] = {{p0.x, p0.y, p0.z, p0.w},
                              {p1.x, p1.y, p1.z, p1.w},
                              {p2.x, p2.y, p2.z, p2.w},
                              {p3.x, p3.y, p3.z, p3.w}};
#pragma unroll
            for (int i = 0; i < 4; i++) {
#pragma unroll
                for (int q = 0; q < 4; q++) {
                    unsigned long long pd = pk2(pr[i][q], pr[i][q]);
                    fma2(o2a[i][0], pd, vq[q][0]);
                    fma2(o2a[i][1], pd, vq[q][1]);
                }
            }
        }
        __syncthreads();
#pragma unroll
        for (int i = 0; i < 4; i++) {
            int d = ty * 4 + i;
            size_t row = (size_t)b * 4096 + (size_t)d * 64 + h * 4 + ch;
            int col = n0 + tx * 4;
            float2 u0 = upk2(o2a[i][0]), u1 = upk2(o2a[i][1]);
            float vv[4] = {u0.x, u0.y, u1.x, u1.y};
            __nv_bfloat16 hi[4], lo[4];
#pragma unroll
            for (int j = 0; j < 4; j++) split1(vv[j], hi[j], lo[j]);
            *reinterpret_cast<uint2*>(O2 + row * K2_ + col) = *reinterpret_cast<uint2*>(hi);
            *reinterpret_cast<uint2*>(O2 + row * K2_ + 1024 + col) = *reinterpret_cast<uint2*>(lo);
        }
    }
}

// ---------------- host ----------------
typedef CUresult (*EncodeTiledFn)(
    CUtensorMap*, CUtensorMapDataType, cuuint32_t, void*,
    const cuuint64_t*, const cuuint64_t*, const cuuint32_t*, const cuuint32_t*,
    CUtensorMapInterleave, CUtensorMapSwizzle, CUtensorMapL2promotion,
    CUtensorMapFloatOOBfill);

static void make_tm(EncodeTiledFn enc, CUtensorMap* tm, void* ptr,
                    unsigned long long rows, unsigned long long cols) {
    cuuint64_t dims[2] = {cols, rows};
    cuuint64_t strides[1] = {cols * 2};
    cuuint32_t box[2] = {64, 128};
    cuuint32_t es[2] = {1, 1};
    enc(tm, CU_TENSOR_MAP_DATA_TYPE_BFLOAT16, 2, ptr, dims, strides, box, es,
        CU_TENSOR_MAP_INTERLEAVE_NONE, CU_TENSOR_MAP_SWIZZLE_128B,
        CU_TENSOR_MAP_L2_PROMOTION_L2_128B, CU_TENSOR_MAP_FLOAT_OOB_FILL_NONE);
}

extern "C" void kernel_launch(void* const* d_in, const int* in_sizes, int n_in,
                              void* d_out, int out_size)
{
    const float* x  = (const float*)d_in[0];
    const float* Wq = (const float*)d_in[1];
    const float* Wk = (const float*)d_in[2];
    const float* Wv = (const float*)d_in[3];
    const float* Wp = (const float*)d_in[4];
    const float* bp = (const float*)d_in[5];
    float* out = (float*)d_out;

    __nv_bfloat16 *x2, *xt2, *w2, *g2, *o2;
    float *T, *v, *p;
    cudaGetSymbolAddress((void**)&x2, g_x2);
    cudaGetSymbolAddress((void**)&xt2, g_xt2);
    cudaGetSymbolAddress((void**)&w2, g_w2);
    cudaGetSymbolAddress((void**)&g2, g_g2);
    cudaGetSymbolAddress((void**)&T, g_T);
    cudaGetSymbolAddress((void**)&v, g_v);
    cudaGetSymbolAddress((void**)&p, g_p);
    cudaGetSymbolAddress((void**)&o2, g_o2);

    // driver-API tensormap encoder via dlopen (no -lcuda link dependency)
    void* h = dlopen("libcuda.so.1", RTLD_NOW | RTLD_GLOBAL);
    if (!h) h = dlopen("libcuda.so", RTLD_NOW | RTLD_GLOBAL);
    EncodeTiledFn enc = (EncodeTiledFn)dlsym(h, "cuTensorMapEncodeTiled");

    const size_t wStride = (size_t)C_ * K2_;
    __nv_bfloat16* wq2 = w2;
    __nv_bfloat16* wv2 = w2 + wStride;
    __nv_bfloat16* wp2 = w2 + 2 * wStride;

    CUtensorMap tm_x2, tm_wq, tm_wv, tm_wp, tm_g2, tm_xt2, tm_o2;
    make_tm(enc, &tm_x2, x2, 32768ull, 2048ull);
    make_tm(enc, &tm_wq, wq2, 1024ull, 2048ull);
    make_tm(enc, &tm_wv, wv2, 1024ull, 2048ull);
    make_tm(enc, &tm_wp, wp2, 1024ull, 2048ull);
    make_tm(enc, &tm_g2, g2, 8192ull, 2048ull);
    make_tm(enc, &tm_xt2, xt2, 8192ull, 8192ull);
    make_tm(enc, &tm_o2, o2, 32768ull, 2048ull);

    auto* kV = gemm_tma<0, 48, false, false, false>;
    auto* kF = gemm_tma<0, 48, false, true, false>;
    auto* kG = gemm_tma<1, 192, true, false, true>;
    cudaFuncSetAttribute(kV, cudaFuncAttributeMaxDynamicSharedMemorySize, GSMEM_SZ);
    cudaFuncSetAttribute(kF, cudaFuncAttributeMaxDynamicSharedMemorySize, GSMEM_SZ);
    cudaFuncSetAttribute(kG, cudaFuncAttributeMaxDynamicSharedMemorySize, GSMEM_SZ);

    // prep
    prep_x<<<dim3(128, 32, 8), dim3(32, 8)>>>(x, x2, xt2);
    split_kernel<<<(C_ * C_ / 4 + 255) / 256, 256>>>((const float4*)Wq, wq2, C_ * C_ / 4);
    split_kernel<<<(C_ * C_ / 4 + 255) / 256, 256>>>((const float4*)Wv, wv2, C_ * C_ / 4);
    split_kernel<<<(C_ * C_ / 4 + 255) / 256, 256>>>((const float4*)Wp, wp2, C_ * C_ / 4);

    // Gram -> split g2 directly (with mirror)
    kG<<<dim3(36, 1, 8), 256, GSMEM_SZ>>>(tm_xt2, tm_xt2, nullptr, g2, C_, C_, 0);

    // V = X Wv^T
    kV<<<dim3(8, 256, 1), 256, GSMEM_SZ>>>(tm_x2, tm_wv, nullptr, v, 0, 0, 0);

    // T_b = Wq * G_b
    kV<<<dim3(8, 8, 8), 256, GSMEM_SZ>>>(tm_wq, tm_g2, nullptr, T, 0, C_, (size_t)C_ * C_);

    // S + softmax -> P ; then O = P V (split output)
    attn_mid<<<128, 256>>>(T, Wk, p);
    attn_pv<<<512, 256>>>(v, p, o2);

    // out = O' Wp^T + bp
    kF<<<dim3(8, 256, 1), 256, GSMEM_SZ>>>(tm_o2, tm_wp, bp, out, 0, 0, 0);

    dlclose(h);
}